// round 1
// baseline (speedup 1.0000x reference)
#include <cuda_runtime.h>
#include <math.h>

#define SEQ 4096
#define HDIM 1024
#define NH 16
#define HD 64

// ---------------- device scratch (static, no allocation) ----------------
__device__ float g_Q[NH * SEQ * HD];    // [h][s][d]
__device__ float g_K[NH * SEQ * HD];
__device__ float g_V[NH * SEQ * HD];
__device__ float g_ctx[SEQ * HDIM];     // [s][h*64+d]
__device__ float g_cos[SEQ * HD];
__device__ float g_sin[SEQ * HD];

#define OUTER4(acc, a, b)                                                        \
    acc[0][0] += a.x * b.x; acc[0][1] += a.x * b.y; acc[0][2] += a.x * b.z; acc[0][3] += a.x * b.w; \
    acc[1][0] += a.y * b.x; acc[1][1] += a.y * b.y; acc[1][2] += a.y * b.z; acc[1][3] += a.y * b.w; \
    acc[2][0] += a.z * b.x; acc[2][1] += a.z * b.y; acc[2][2] += a.z * b.z; acc[2][3] += a.z * b.w; \
    acc[3][0] += a.w * b.x; acc[3][1] += a.w * b.y; acc[3][2] += a.w * b.z; acc[3][3] += a.w * b.w;

// ---------------- RoPE tables (one-time-ish, tiny) ----------------
__global__ void rope_tables_kernel() {
    int idx = blockIdx.x * 256 + threadIdx.x;
    if (idx >= SEQ * HD) return;
    int t = idx >> 6;
    int j = idx & 63;
    int i = j & 31;  // emb = concat(freqs, freqs): col j -> inv_freq[j mod 32]
    double inv = pow(10000.0, -(double)(2 * i) / 64.0);
    double ang = (double)t * inv;
    g_cos[idx] = (float)cos(ang);
    g_sin[idx] = (float)sin(ang);
}

// ---------------- fused QKV projection + RoPE epilogue ----------------
// C = x @ W ; 64x64x16 tiles, 256 threads, 4x4 micro-tile.
// grid (HDIM/64=16, SEQ/64=64, 3); z selects Wq/Wk/Wv. blockIdx.x == head.
__global__ void __launch_bounds__(256) qkv_gemm_kernel(
    const float* __restrict__ x,
    const float* __restrict__ Wq,
    const float* __restrict__ Wk,
    const float* __restrict__ Wv)
{
    const int z = blockIdx.z;
    const float* W = (z == 0) ? Wq : ((z == 1) ? Wk : Wv);
    float* dst = (z == 0) ? g_Q : ((z == 1) ? g_K : g_V);

    __shared__ float As[16][68];  // [k][m]  (A transposed)
    __shared__ float Bs[16][68];  // [k][n]

    const int tid = threadIdx.x;
    const int tx = tid & 15, ty = tid >> 4;
    const int s0 = blockIdx.y * 64;
    const int n0 = blockIdx.x * 64;

    const int arow = tid >> 2, akq = (tid & 3) * 4;
    const int brow = tid >> 4, bnq = (tid & 15) * 4;

    float acc[4][4] = {};

    for (int k0 = 0; k0 < HDIM; k0 += 16) {
        float4 av = *(const float4*)&x[(size_t)(s0 + arow) * HDIM + k0 + akq];
        As[akq + 0][arow] = av.x; As[akq + 1][arow] = av.y;
        As[akq + 2][arow] = av.z; As[akq + 3][arow] = av.w;
        float4 bv = *(const float4*)&W[(size_t)(k0 + brow) * HDIM + n0 + bnq];
        *(float4*)&Bs[brow][bnq] = bv;
        __syncthreads();
#pragma unroll
        for (int kk = 0; kk < 16; kk++) {
            float4 a = *(float4*)&As[kk][ty * 4];
            float4 b = *(float4*)&Bs[kk][tx * 4];
            OUTER4(acc, a, b);
        }
        __syncthreads();
    }

    // epilogue: RoPE for Q,K ; raw for V. head = blockIdx.x, d = tx*4+j
#pragma unroll
    for (int i = 0; i < 4; i++) {
        int srow = s0 + ty * 4 + i;
#pragma unroll
        for (int jp = 0; jp < 2; jp++) {
            int d0 = tx * 4 + jp * 2;
            float v0 = acc[i][jp * 2 + 0];
            float v1 = acc[i][jp * 2 + 1];
            float o0, o1;
            if (z < 2) {
                float c0 = g_cos[srow * HD + d0];
                float s0v = g_sin[srow * HD + d0];
                float c1 = g_cos[srow * HD + d0 + 1];
                float s1v = g_sin[srow * HD + d0 + 1];
                o0 = v0 * c0 - v1 * s0v;   // even: x*cos - x_odd*sin
                o1 = v1 * c1 + v0 * s1v;   // odd:  x*cos + x_even*sin
            } else {
                o0 = v0; o1 = v1;
            }
            size_t base = (size_t)blockIdx.x * SEQ * HD + (size_t)srow * HD + d0;
            dst[base] = o0;
            dst[base + 1] = o1;
        }
    }
}

// ---------------- flash attention (fp32, online softmax) ----------------
// grid (SEQ/64=64 qblocks, NH=16 heads), 256 threads, dynamic smem.
#define FA_SMEM (4 * 64 * 68 * 4 + 64 * 4)

__global__ void __launch_bounds__(256) flash_attn_kernel(const int* __restrict__ mask) {
    extern __shared__ float sm[];
    float* Qt = sm;             // [d][q]  64x68
    float* Kt = Qt + 64 * 68;   // [d][k]
    float* Vs = Kt + 64 * 68;   // [k][d]
    float* Ps = Vs + 64 * 68;   // [k][q]
    int* msk = (int*)(Ps + 64 * 68);

    const int tid = threadIdx.x;
    const int tx = tid & 15, ty = tid >> 4;
    const int q0 = blockIdx.x * 64;
    const int h = blockIdx.y;

    const float* Qg = g_Q + (size_t)h * SEQ * HD;
    const float* Kg = g_K + (size_t)h * SEQ * HD;
    const float* Vg = g_V + (size_t)h * SEQ * HD;

    // load Q tile transposed (once)
#pragma unroll
    for (int ii = 0; ii < 4; ii++) {
        int row = (tid >> 4) + ii * 16;
        int dq = (tid & 15) * 4;
        float4 v = *(const float4*)&Qg[(size_t)(q0 + row) * HD + dq];
        Qt[(dq + 0) * 68 + row] = v.x; Qt[(dq + 1) * 68 + row] = v.y;
        Qt[(dq + 2) * 68 + row] = v.z; Qt[(dq + 3) * 68 + row] = v.w;
    }

    float accO[4][4] = {};
    float mrow[4] = {-3e38f, -3e38f, -3e38f, -3e38f};
    float lrow[4] = {};
    const float scale = 0.125f;  // 1/sqrt(64)

    for (int kb = 0; kb < SEQ / 64; kb++) {
        const int k0 = kb * 64;
        __syncthreads();  // prior iteration fully done with Kt/Vs/Ps (and Qt load visible)
#pragma unroll
        for (int ii = 0; ii < 4; ii++) {
            int row = (tid >> 4) + ii * 16;
            int dq = (tid & 15) * 4;
            float4 kv = *(const float4*)&Kg[(size_t)(k0 + row) * HD + dq];
            Kt[(dq + 0) * 68 + row] = kv.x; Kt[(dq + 1) * 68 + row] = kv.y;
            Kt[(dq + 2) * 68 + row] = kv.z; Kt[(dq + 3) * 68 + row] = kv.w;
            float4 vv = *(const float4*)&Vg[(size_t)(k0 + row) * HD + dq];
            *(float4*)&Vs[row * 68 + dq] = vv;
        }
        if (tid < 64) msk[tid] = mask[k0 + tid];
        __syncthreads();

        // S = Q K^T
        float sacc[4][4] = {};
#pragma unroll 8
        for (int d = 0; d < 64; d++) {
            float4 a = *(float4*)&Qt[d * 68 + ty * 4];
            float4 b = *(float4*)&Kt[d * 68 + tx * 4];
            OUTER4(sacc, a, b);
        }

        int mk[4];
#pragma unroll
        for (int j = 0; j < 4; j++) mk[j] = msk[tx * 4 + j];
#pragma unroll
        for (int i = 0; i < 4; i++)
#pragma unroll
            for (int j = 0; j < 4; j++) {
                float sv = sacc[i][j] * scale;
                sacc[i][j] = (mk[j] == 0) ? -1e30f : sv;
            }

        // online softmax per query row (row spread over 16 tx lanes)
#pragma unroll
        for (int i = 0; i < 4; i++) {
            float tm = fmaxf(fmaxf(sacc[i][0], sacc[i][1]), fmaxf(sacc[i][2], sacc[i][3]));
            tm = fmaxf(tm, __shfl_xor_sync(0xffffffffu, tm, 1));
            tm = fmaxf(tm, __shfl_xor_sync(0xffffffffu, tm, 2));
            tm = fmaxf(tm, __shfl_xor_sync(0xffffffffu, tm, 4));
            tm = fmaxf(tm, __shfl_xor_sync(0xffffffffu, tm, 8));
            float mnew = fmaxf(mrow[i], tm);
            float corr = __expf(mrow[i] - mnew);
            float rsum = 0.f;
#pragma unroll
            for (int j = 0; j < 4; j++) {
                float p = __expf(sacc[i][j] - mnew);
                sacc[i][j] = p;
                rsum += p;
            }
            rsum += __shfl_xor_sync(0xffffffffu, rsum, 1);
            rsum += __shfl_xor_sync(0xffffffffu, rsum, 2);
            rsum += __shfl_xor_sync(0xffffffffu, rsum, 4);
            rsum += __shfl_xor_sync(0xffffffffu, rsum, 8);
            lrow[i] = lrow[i] * corr + rsum;
            mrow[i] = mnew;
#pragma unroll
            for (int j = 0; j < 4; j++) accO[i][j] *= corr;
        }

        // stage P transposed: Ps[k][q]
#pragma unroll
        for (int j = 0; j < 4; j++) {
            float4 pv = make_float4(sacc[0][j], sacc[1][j], sacc[2][j], sacc[3][j]);
            *(float4*)&Ps[(tx * 4 + j) * 68 + ty * 4] = pv;
        }
        __syncthreads();

        // O += P V
#pragma unroll 8
        for (int k = 0; k < 64; k++) {
            float4 a = *(float4*)&Ps[k * 68 + ty * 4];
            float4 b = *(float4*)&Vs[k * 68 + tx * 4];
            OUTER4(accO, a, b);
        }
    }

    // epilogue: normalize and write ctx [s][h*64+d]
#pragma unroll
    for (int i = 0; i < 4; i++) {
        float inv = 1.0f / lrow[i];
        int srow = q0 + ty * 4 + i;
        float4 o = make_float4(accO[i][0] * inv, accO[i][1] * inv,
                               accO[i][2] * inv, accO[i][3] * inv);
        *(float4*)&g_ctx[(size_t)srow * HDIM + h * HD + tx * 4] = o;
    }
}

// ---------------- output projection: out = ctx @ Wo ----------------
__global__ void __launch_bounds__(256) out_proj_kernel(
    const float* __restrict__ Wo, float* __restrict__ out)
{
    __shared__ float As[16][68];
    __shared__ float Bs[16][68];

    const int tid = threadIdx.x;
    const int tx = tid & 15, ty = tid >> 4;
    const int s0 = blockIdx.y * 64;
    const int n0 = blockIdx.x * 64;

    const int arow = tid >> 2, akq = (tid & 3) * 4;
    const int brow = tid >> 4, bnq = (tid & 15) * 4;

    float acc[4][4] = {};

    for (int k0 = 0; k0 < HDIM; k0 += 16) {
        float4 av = *(const float4*)&g_ctx[(size_t)(s0 + arow) * HDIM + k0 + akq];
        As[akq + 0][arow] = av.x; As[akq + 1][arow] = av.y;
        As[akq + 2][arow] = av.z; As[akq + 3][arow] = av.w;
        float4 bv = *(const float4*)&Wo[(size_t)(k0 + brow) * HDIM + n0 + bnq];
        *(float4*)&Bs[brow][bnq] = bv;
        __syncthreads();
#pragma unroll
        for (int kk = 0; kk < 16; kk++) {
            float4 a = *(float4*)&As[kk][ty * 4];
            float4 b = *(float4*)&Bs[kk][tx * 4];
            OUTER4(acc, a, b);
        }
        __syncthreads();
    }

#pragma unroll
    for (int i = 0; i < 4; i++) {
        int srow = s0 + ty * 4 + i;
        float4 o = make_float4(acc[i][0], acc[i][1], acc[i][2], acc[i][3]);
        *(float4*)&out[(size_t)srow * HDIM + n0 + tx * 4] = o;
    }
}

// ---------------- launch ----------------
extern "C" void kernel_launch(void* const* d_in, const int* in_sizes, int n_in,
                              void* d_out, int out_size) {
    const float* x  = (const float*)d_in[0];
    const float* Wq = (const float*)d_in[1];
    const float* Wk = (const float*)d_in[2];
    const float* Wv = (const float*)d_in[3];
    const float* Wo = (const float*)d_in[4];
    const int* mask = (const int*)d_in[5];
    float* out = (float*)d_out;

    cudaFuncSetAttribute(flash_attn_kernel,
                         cudaFuncAttributeMaxDynamicSharedMemorySize, FA_SMEM);

    rope_tables_kernel<<<(SEQ * HD + 255) / 256, 256>>>();
    qkv_gemm_kernel<<<dim3(HDIM / 64, SEQ / 64, 3), 256>>>(x, Wq, Wk, Wv);
    flash_attn_kernel<<<dim3(SEQ / 64, NH), 256, FA_SMEM>>>(mask);
    out_proj_kernel<<<dim3(HDIM / 64, SEQ / 64), 256>>>(Wo, out);
}

// round 2
// speedup vs baseline: 2.9566x; 2.9566x over previous
#include <cuda_runtime.h>
#include <math.h>

#define SEQ 4096
#define HDIM 1024
#define NH 16
#define HD 64

// ---------------- device scratch ----------------
__device__ float g_Q[NH * SEQ * HD];
__device__ float g_K[NH * SEQ * HD];
__device__ float g_V[NH * SEQ * HD];
__device__ float g_ctx[SEQ * HDIM];
__device__ float g_cos[SEQ * HD];
__device__ float g_sin[SEQ * HD];

// ---------------- helpers ----------------
__device__ __forceinline__ unsigned f2t(float f) {
    unsigned u;
    asm("cvt.rna.tf32.f32 %0, %1;" : "=r"(u) : "f"(f));
    return u;
}

__device__ __forceinline__ void mma8(float* c, const unsigned* a, const unsigned* b) {
    asm volatile(
        "mma.sync.aligned.m16n8k8.row.col.f32.tf32.tf32.f32 "
        "{%0,%1,%2,%3}, {%4,%5,%6,%7}, {%8,%9}, {%0,%1,%2,%3};\n"
        : "+f"(c[0]), "+f"(c[1]), "+f"(c[2]), "+f"(c[3])
        : "r"(a[0]), "r"(a[1]), "r"(a[2]), "r"(a[3]), "r"(b[0]), "r"(b[1]));
}

// ---------------- RoPE tables ----------------
__global__ void rope_tables_kernel() {
    int idx = blockIdx.x * 256 + threadIdx.x;
    if (idx >= SEQ * HD) return;
    int t = idx >> 6;
    int j = idx & 63;
    int i = j & 31;
    double inv = pow(10000.0, -(double)(2 * i) / 64.0);
    double ang = (double)t * inv;
    g_cos[idx] = (float)cos(ang);
    g_sin[idx] = (float)sin(ang);
}

// ---------------- GEMM core (tf32 mma): C[128x64] tile of A[4096x1024] @ W[1024x64-slice]
// 256 threads = 8 warps (4 M x 2 N); warp tile m32 x n32; K-step 32.
// As stride 36 (==4 mod 32), Bs stride 72 (==8 mod 32): conflict-free frag LDS.
#define AS_STRIDE 36
#define BS_STRIDE 72

__device__ __forceinline__ void gemm_core_128x64(
    const float* __restrict__ A, const float* __restrict__ W,
    int s0, int n0, float acc[2][4][4], unsigned* As, unsigned* Bs)
{
    const int tid = threadIdx.x;
    const int lane = tid & 31;
    const int warp = tid >> 5;
    const int wm = warp & 3;
    const int wn = warp >> 2;
    const int gid = lane >> 2;
    const int tig = lane & 3;

    for (int k0 = 0; k0 < HDIM; k0 += 32) {
        __syncthreads();
        // load A tile 128x32 (4 float4 per thread), convert to tf32
#pragma unroll
        for (int i = 0; i < 4; i++) {
            int f = tid + 256 * i;
            int row = f >> 3;
            int c4 = (f & 7) * 4;
            float4 v = *(const float4*)&A[(size_t)(s0 + row) * HDIM + k0 + c4];
            uint4 u = make_uint4(f2t(v.x), f2t(v.y), f2t(v.z), f2t(v.w));
            *(uint4*)&As[row * AS_STRIDE + c4] = u;
        }
        // load B tile 32x64 (2 float4 per thread)
#pragma unroll
        for (int i = 0; i < 2; i++) {
            int f = tid + 256 * i;
            int row = f >> 4;
            int c4 = (f & 15) * 4;
            float4 v = *(const float4*)&W[(size_t)(k0 + row) * HDIM + n0 + c4];
            uint4 u = make_uint4(f2t(v.x), f2t(v.y), f2t(v.z), f2t(v.w));
            *(uint4*)&Bs[row * BS_STRIDE + c4] = u;
        }
        __syncthreads();

#pragma unroll
        for (int g = 0; g < 4; g++) {
            unsigned a0[4], a1[4];
            int qb = wm * 32;
            a0[0] = As[(qb + gid) * AS_STRIDE + g * 8 + tig];
            a0[1] = As[(qb + gid + 8) * AS_STRIDE + g * 8 + tig];
            a0[2] = As[(qb + gid) * AS_STRIDE + g * 8 + tig + 4];
            a0[3] = As[(qb + gid + 8) * AS_STRIDE + g * 8 + tig + 4];
            a1[0] = As[(qb + 16 + gid) * AS_STRIDE + g * 8 + tig];
            a1[1] = As[(qb + 16 + gid + 8) * AS_STRIDE + g * 8 + tig];
            a1[2] = As[(qb + 16 + gid) * AS_STRIDE + g * 8 + tig + 4];
            a1[3] = As[(qb + 16 + gid + 8) * AS_STRIDE + g * 8 + tig + 4];
#pragma unroll
            for (int na = 0; na < 4; na++) {
                unsigned b[2];
                int n = wn * 32 + na * 8 + gid;
                b[0] = Bs[(g * 8 + tig) * BS_STRIDE + n];
                b[1] = Bs[(g * 8 + tig + 4) * BS_STRIDE + n];
                mma8(acc[0][na], a0, b);
                mma8(acc[1][na], a1, b);
            }
        }
    }
}

// ---------------- QKV projection + RoPE ----------------
// grid (16 heads, 32 m-blocks, 3), 256 threads
__global__ void __launch_bounds__(256) qkv_kernel(
    const float* __restrict__ x,
    const float* __restrict__ Wq,
    const float* __restrict__ Wk,
    const float* __restrict__ Wv)
{
    __shared__ unsigned As[128 * AS_STRIDE];
    __shared__ unsigned Bs[32 * BS_STRIDE];

    const int z = blockIdx.z;
    const float* W = (z == 0) ? Wq : ((z == 1) ? Wk : Wv);
    float* dst = (z == 0) ? g_Q : ((z == 1) ? g_K : g_V);

    const int tid = threadIdx.x;
    const int lane = tid & 31;
    const int warp = tid >> 5;
    const int wm = warp & 3;
    const int wn = warp >> 2;
    const int gid = lane >> 2;
    const int tig = lane & 3;
    const int s0 = blockIdx.y * 128;
    const int n0 = blockIdx.x * 64;
    const int head = blockIdx.x;

    float acc[2][4][4] = {};
    gemm_core_128x64(x, W, s0, n0, acc, As, Bs);

    // epilogue
#pragma unroll
    for (int ma = 0; ma < 2; ma++) {
#pragma unroll
        for (int na = 0; na < 4; na++) {
#pragma unroll
            for (int rr = 0; rr < 2; rr++) {
                int row = s0 + wm * 32 + ma * 16 + gid + rr * 8;
                int d = wn * 32 + na * 8 + 2 * tig;
                float v0 = acc[ma][na][2 * rr + 0];
                float v1 = acc[ma][na][2 * rr + 1];
                float o0, o1;
                if (z < 2) {
                    float c0 = g_cos[row * HD + d];
                    float s0v = g_sin[row * HD + d];
                    float c1 = g_cos[row * HD + d + 1];
                    float s1v = g_sin[row * HD + d + 1];
                    o0 = v0 * c0 - v1 * s0v;
                    o1 = v1 * c1 + v0 * s1v;
                } else {
                    o0 = v0; o1 = v1;
                }
                float2* p = (float2*)&dst[(size_t)head * SEQ * HD + (size_t)row * HD + d];
                *p = make_float2(o0, o1);
            }
        }
    }
}

// ---------------- output projection ----------------
__global__ void __launch_bounds__(256) oproj_kernel(
    const float* __restrict__ Wo, float* __restrict__ out)
{
    __shared__ unsigned As[128 * AS_STRIDE];
    __shared__ unsigned Bs[32 * BS_STRIDE];

    const int tid = threadIdx.x;
    const int lane = tid & 31;
    const int warp = tid >> 5;
    const int wm = warp & 3;
    const int wn = warp >> 2;
    const int gid = lane >> 2;
    const int tig = lane & 3;
    const int s0 = blockIdx.y * 128;
    const int n0 = blockIdx.x * 64;

    float acc[2][4][4] = {};
    gemm_core_128x64(g_ctx, Wo, s0, n0, acc, As, Bs);

#pragma unroll
    for (int ma = 0; ma < 2; ma++)
#pragma unroll
        for (int na = 0; na < 4; na++)
#pragma unroll
            for (int rr = 0; rr < 2; rr++) {
                int row = s0 + wm * 32 + ma * 16 + gid + rr * 8;
                int col = n0 + wn * 32 + na * 8 + 2 * tig;
                *(float2*)&out[(size_t)row * HDIM + col] =
                    make_float2(acc[ma][na][2 * rr + 0], acc[ma][na][2 * rr + 1]);
            }
}

// ---------------- flash attention (tf32 mma) ----------------
// grid (32 qblocks, 16 heads), 128 threads (4 warps, m32 each), k-tile 64.
#define QS_STRIDE 68   // == 4 mod 32
#define KS_STRIDE 68   // == 4 mod 32
#define VS_STRIDE 72   // == 8 mod 32
#define PS_STRIDE 68

#define ATT_SMEM ((128 * QS_STRIDE + 128 * PS_STRIDE + 64 * KS_STRIDE + 64 * VS_STRIDE + 64) * 4)

__global__ void __launch_bounds__(128) attn_kernel(const int* __restrict__ mask) {
    extern __shared__ unsigned sm_u[];
    unsigned* Qs = sm_u;
    unsigned* Ps = Qs + 128 * QS_STRIDE;
    unsigned* Ks = Ps + 128 * PS_STRIDE;
    unsigned* Vs = Ks + 64 * KS_STRIDE;
    float* sbias = (float*)(Vs + 64 * VS_STRIDE);

    const int tid = threadIdx.x;
    const int lane = tid & 31;
    const int w = tid >> 5;
    const int gid = lane >> 2;
    const int tig = lane & 3;
    const int q0 = blockIdx.x * 128;
    const int h = blockIdx.y;

    const float* Qg = g_Q + (size_t)h * SEQ * HD;
    const float* Kg = g_K + (size_t)h * SEQ * HD;
    const float* Vg = g_V + (size_t)h * SEQ * HD;

    // stage Q (tf32)
#pragma unroll
    for (int i = 0; i < 16; i++) {
        int f = tid + 128 * i;
        int row = f >> 4;
        int c4 = (f & 15) * 4;
        float4 v = *(const float4*)&Qg[(size_t)(q0 + row) * HD + c4];
        uint4 u = make_uint4(f2t(v.x), f2t(v.y), f2t(v.z), f2t(v.w));
        *(uint4*)&Qs[row * QS_STRIDE + c4] = u;
    }

    float Oacc[2][8][4] = {};
    float mrow[4] = {-1e30f, -1e30f, -1e30f, -1e30f};
    float lrow[4] = {0.f, 0.f, 0.f, 0.f};
    const int qb = w * 32;

    for (int kt = 0; kt < SEQ / 64; kt++) {
        const int k0 = kt * 64;
        __syncthreads();
#pragma unroll
        for (int i = 0; i < 8; i++) {
            int f = tid + 128 * i;
            int row = f >> 4;
            int c4 = (f & 15) * 4;
            float4 kv = *(const float4*)&Kg[(size_t)(k0 + row) * HD + c4];
            *(uint4*)&Ks[row * KS_STRIDE + c4] =
                make_uint4(f2t(kv.x), f2t(kv.y), f2t(kv.z), f2t(kv.w));
            float4 vv = *(const float4*)&Vg[(size_t)(k0 + row) * HD + c4];
            *(uint4*)&Vs[row * VS_STRIDE + c4] =
                make_uint4(f2t(vv.x), f2t(vv.y), f2t(vv.z), f2t(vv.w));
        }
        if (tid < 64) sbias[tid] = (mask[k0 + tid] == 0) ? -1e30f : 0.f;
        __syncthreads();

        // ---- S = Q K^T ----
        float sacc[2][8][4] = {};
#pragma unroll
        for (int g = 0; g < 8; g++) {
            unsigned a0[4], a1[4];
            a0[0] = Qs[(qb + gid) * QS_STRIDE + g * 8 + tig];
            a0[1] = Qs[(qb + gid + 8) * QS_STRIDE + g * 8 + tig];
            a0[2] = Qs[(qb + gid) * QS_STRIDE + g * 8 + tig + 4];
            a0[3] = Qs[(qb + gid + 8) * QS_STRIDE + g * 8 + tig + 4];
            a1[0] = Qs[(qb + 16 + gid) * QS_STRIDE + g * 8 + tig];
            a1[1] = Qs[(qb + 16 + gid + 8) * QS_STRIDE + g * 8 + tig];
            a1[2] = Qs[(qb + 16 + gid) * QS_STRIDE + g * 8 + tig + 4];
            a1[3] = Qs[(qb + 16 + gid + 8) * QS_STRIDE + g * 8 + tig + 4];
#pragma unroll
            for (int na = 0; na < 8; na++) {
                unsigned b[2];
                int key = na * 8 + gid;
                b[0] = Ks[key * KS_STRIDE + g * 8 + tig];
                b[1] = Ks[key * KS_STRIDE + g * 8 + tig + 4];
                mma8(sacc[0][na], a0, b);
                mma8(sacc[1][na], a1, b);
            }
        }

        // bias regs
        float bb[8][2];
#pragma unroll
        for (int na = 0; na < 8; na++) {
            bb[na][0] = sbias[na * 8 + 2 * tig];
            bb[na][1] = sbias[na * 8 + 2 * tig + 1];
        }

        // ---- online softmax ----
#pragma unroll
        for (int ma = 0; ma < 2; ma++) {
#pragma unroll
            for (int rr = 0; rr < 2; rr++) {
                const int li = ma * 2 + rr;
                float mt = -1e30f;
#pragma unroll
                for (int na = 0; na < 8; na++) {
#pragma unroll
                    for (int s = 0; s < 2; s++) {
                        float v = sacc[ma][na][2 * rr + s] * 0.125f + bb[na][s];
                        sacc[ma][na][2 * rr + s] = v;
                        mt = fmaxf(mt, v);
                    }
                }
                mt = fmaxf(mt, __shfl_xor_sync(0xffffffffu, mt, 1));
                mt = fmaxf(mt, __shfl_xor_sync(0xffffffffu, mt, 2));
                float mnew = fmaxf(mrow[li], mt);
                float corr = __expf(mrow[li] - mnew);
                float rs = 0.f;
#pragma unroll
                for (int na = 0; na < 8; na++) {
#pragma unroll
                    for (int s = 0; s < 2; s++) {
                        float p = __expf(sacc[ma][na][2 * rr + s] - mnew);
                        sacc[ma][na][2 * rr + s] = p;
                        rs += p;
                    }
                }
                rs += __shfl_xor_sync(0xffffffffu, rs, 1);
                rs += __shfl_xor_sync(0xffffffffu, rs, 2);
                lrow[li] = lrow[li] * corr + rs;
                mrow[li] = mnew;
#pragma unroll
                for (int nd = 0; nd < 8; nd++) {
                    Oacc[ma][nd][2 * rr + 0] *= corr;
                    Oacc[ma][nd][2 * rr + 1] *= corr;
                }
            }
        }

        // ---- stage P (tf32) ----
#pragma unroll
        for (int ma = 0; ma < 2; ma++) {
#pragma unroll
            for (int na = 0; na < 8; na++) {
                int r0 = qb + ma * 16 + gid;
                int c = na * 8 + 2 * tig;
                Ps[r0 * PS_STRIDE + c] = f2t(sacc[ma][na][0]);
                Ps[r0 * PS_STRIDE + c + 1] = f2t(sacc[ma][na][1]);
                Ps[(r0 + 8) * PS_STRIDE + c] = f2t(sacc[ma][na][2]);
                Ps[(r0 + 8) * PS_STRIDE + c + 1] = f2t(sacc[ma][na][3]);
            }
        }
        __syncwarp();

        // ---- O += P V ----
#pragma unroll
        for (int g = 0; g < 8; g++) {
            unsigned a0[4], a1[4];
            a0[0] = Ps[(qb + gid) * PS_STRIDE + g * 8 + tig];
            a0[1] = Ps[(qb + gid + 8) * PS_STRIDE + g * 8 + tig];
            a0[2] = Ps[(qb + gid) * PS_STRIDE + g * 8 + tig + 4];
            a0[3] = Ps[(qb + gid + 8) * PS_STRIDE + g * 8 + tig + 4];
            a1[0] = Ps[(qb + 16 + gid) * PS_STRIDE + g * 8 + tig];
            a1[1] = Ps[(qb + 16 + gid + 8) * PS_STRIDE + g * 8 + tig];
            a1[2] = Ps[(qb + 16 + gid) * PS_STRIDE + g * 8 + tig + 4];
            a1[3] = Ps[(qb + 16 + gid + 8) * PS_STRIDE + g * 8 + tig + 4];
#pragma unroll
            for (int nd = 0; nd < 8; nd++) {
                unsigned b[2];
                int d = nd * 8 + gid;
                b[0] = Vs[(g * 8 + tig) * VS_STRIDE + d];
                b[1] = Vs[(g * 8 + tig + 4) * VS_STRIDE + d];
                mma8(Oacc[0][nd], a0, b);
                mma8(Oacc[1][nd], a1, b);
            }
        }
    }

    // epilogue: normalize + write ctx
    float inv[4];
#pragma unroll
    for (int i = 0; i < 4; i++) inv[i] = 1.0f / lrow[i];
#pragma unroll
    for (int ma = 0; ma < 2; ma++)
#pragma unroll
        for (int nd = 0; nd < 8; nd++)
#pragma unroll
            for (int rr = 0; rr < 2; rr++) {
                int row = q0 + qb + ma * 16 + gid + rr * 8;
                int d = nd * 8 + 2 * tig;
                float iv = inv[ma * 2 + rr];
                *(float2*)&g_ctx[(size_t)row * HDIM + h * HD + d] =
                    make_float2(Oacc[ma][nd][2 * rr] * iv, Oacc[ma][nd][2 * rr + 1] * iv);
            }
}

// ---------------- launch ----------------
extern "C" void kernel_launch(void* const* d_in, const int* in_sizes, int n_in,
                              void* d_out, int out_size) {
    const float* x  = (const float*)d_in[0];
    const float* Wq = (const float*)d_in[1];
    const float* Wk = (const float*)d_in[2];
    const float* Wv = (const float*)d_in[3];
    const float* Wo = (const float*)d_in[4];
    const int* mask = (const int*)d_in[5];
    float* out = (float*)d_out;

    cudaFuncSetAttribute(attn_kernel,
                         cudaFuncAttributeMaxDynamicSharedMemorySize, ATT_SMEM);

    rope_tables_kernel<<<(SEQ * HD + 255) / 256, 256>>>();
    qkv_kernel<<<dim3(NH, SEQ / 128, 3), 256>>>(x, Wq, Wk, Wv);
    attn_kernel<<<dim3(SEQ / 128, NH), 128, ATT_SMEM>>>(mask);
    oproj_kernel<<<dim3(HDIM / 64, SEQ / 128), 256>>>(Wo, out);
}

// round 4
// speedup vs baseline: 3.1528x; 1.0664x over previous
#include <cuda_runtime.h>
#include <math.h>

#define SEQ 4096
#define HDIM 1024
#define NH 16
#define HD 64

// ---------------- device scratch ----------------
__device__ float g_Q[NH * SEQ * HD];
__device__ float g_K[NH * SEQ * HD];
__device__ float g_V[NH * SEQ * HD];
__device__ float g_ctx[SEQ * HDIM];
__device__ float g_cos[SEQ * HD];
__device__ float g_sin[SEQ * HD];

// ---------------- helpers ----------------
__device__ __forceinline__ unsigned f2t(float f) {
    unsigned u;
    asm("cvt.rna.tf32.f32 %0, %1;" : "=r"(u) : "f"(f));
    return u;
}

__device__ __forceinline__ void mma8(float* c, const unsigned* a, const unsigned* b) {
    asm volatile(
        "mma.sync.aligned.m16n8k8.row.col.f32.tf32.tf32.f32 "
        "{%0,%1,%2,%3}, {%4,%5,%6,%7}, {%8,%9}, {%0,%1,%2,%3};\n"
        : "+f"(c[0]), "+f"(c[1]), "+f"(c[2]), "+f"(c[3])
        : "r"(a[0]), "r"(a[1]), "r"(a[2]), "r"(a[3]), "r"(b[0]), "r"(b[1]));
}

__device__ __forceinline__ void cp16(unsigned dst, const void* src) {
    asm volatile("cp.async.cg.shared.global [%0], [%1], 16;" :: "r"(dst), "l"(src));
}

// ---------------- RoPE tables ----------------
// Match reference rounding: angle = fp32(t) * fp32(inv_freq) rounded to fp32.
__global__ void rope_tables_kernel() {
    int idx = blockIdx.x * 256 + threadIdx.x;
    if (idx >= SEQ * HD) return;
    int t = idx >> 6;
    int j = idx & 63;
    int i = j & 31;
    float xe = (float)(2 * i) / 64.0f;
    float pf = (float)pow(10000.0, (double)xe);
    float invf = 1.0f / pf;
    float angf = (float)t * invf;
    double ang = (double)angf;
    g_cos[idx] = (float)cos(ang);
    g_sin[idx] = (float)sin(ang);
}

// ---------------- GEMM core: C[128x64] = A[128,1024] @ W[:,64-slice]
// 256 threads = 8 warps (4 M x 2 N), warp tile m32 x n32, K-step 32,
// cp.async double-buffered raw fp32 tiles, tf32 cvt at fragment load.
// A tile 128x32 (stride 36), B tile 32x64 (stride 72) — both widths COVERED.
#define AS_STRIDE 36   // >=32, ==4 mod 32
#define BS_STRIDE 72   // >=64, ==8 mod 32
#define GEMM_SMEM ((2 * 128 * AS_STRIDE + 2 * 32 * BS_STRIDE) * 4)

__device__ __forceinline__ void gemm_core_128x64(
    const float* __restrict__ A, const float* __restrict__ W,
    int s0, int n0, float acc[2][4][4], float* As2, float* Bs2)
{
    const int tid = threadIdx.x;
    const int lane = tid & 31;
    const int warp = tid >> 5;
    const int wm = warp & 3;
    const int wn = warp >> 2;
    const int gid = lane >> 2;
    const int tig = lane & 3;
    const int qb = wm * 32;

    unsigned asb = (unsigned)__cvta_generic_to_shared(As2);
    unsigned bsb = (unsigned)__cvta_generic_to_shared(Bs2);

    auto issue = [&](int k0, int buf) {
#pragma unroll
        for (int i = 0; i < 4; i++) {
            int f = tid + 256 * i;
            int row = f >> 3, c4 = (f & 7) * 4;   // 128 rows x 32 cols
            cp16(asb + (unsigned)(buf * 128 * AS_STRIDE + row * AS_STRIDE + c4) * 4u,
                 &A[(size_t)(s0 + row) * HDIM + k0 + c4]);
        }
#pragma unroll
        for (int i = 0; i < 2; i++) {
            int f = tid + 256 * i;
            int row = f >> 4, c4 = (f & 15) * 4;  // 32 rows x 64 cols
            cp16(bsb + (unsigned)(buf * 32 * BS_STRIDE + row * BS_STRIDE + c4) * 4u,
                 &W[(size_t)(k0 + row) * HDIM + n0 + c4]);
        }
    };

    issue(0, 0);
    asm volatile("cp.async.commit_group;");
    int buf = 0;

    for (int k0 = 0; k0 < HDIM; k0 += 32) {
        if (k0 + 32 < HDIM) {
            issue(k0 + 32, buf ^ 1);
            asm volatile("cp.async.commit_group;");
            asm volatile("cp.async.wait_group 1;");
        } else {
            asm volatile("cp.async.wait_group 0;");
        }
        __syncthreads();

        const float* Af = As2 + buf * 128 * AS_STRIDE;
        const float* Bf = Bs2 + buf * 32 * BS_STRIDE;
#pragma unroll
        for (int g = 0; g < 4; g++) {
            unsigned a0[4], a1[4];
            a0[0] = f2t(Af[(qb + gid) * AS_STRIDE + g * 8 + tig]);
            a0[1] = f2t(Af[(qb + gid + 8) * AS_STRIDE + g * 8 + tig]);
            a0[2] = f2t(Af[(qb + gid) * AS_STRIDE + g * 8 + tig + 4]);
            a0[3] = f2t(Af[(qb + gid + 8) * AS_STRIDE + g * 8 + tig + 4]);
            a1[0] = f2t(Af[(qb + 16 + gid) * AS_STRIDE + g * 8 + tig]);
            a1[1] = f2t(Af[(qb + 16 + gid + 8) * AS_STRIDE + g * 8 + tig]);
            a1[2] = f2t(Af[(qb + 16 + gid) * AS_STRIDE + g * 8 + tig + 4]);
            a1[3] = f2t(Af[(qb + 16 + gid + 8) * AS_STRIDE + g * 8 + tig + 4]);
#pragma unroll
            for (int na = 0; na < 4; na++) {
                unsigned b[2];
                int n = wn * 32 + na * 8 + gid;
                b[0] = f2t(Bf[(g * 8 + tig) * BS_STRIDE + n]);
                b[1] = f2t(Bf[(g * 8 + tig + 4) * BS_STRIDE + n]);
                mma8(acc[0][na], a0, b);
                mma8(acc[1][na], a1, b);
            }
        }
        buf ^= 1;
        __syncthreads();
    }
}

// ---------------- QKV projection + RoPE ----------------
__global__ void __launch_bounds__(256) qkv_kernel(
    const float* __restrict__ x,
    const float* __restrict__ Wq,
    const float* __restrict__ Wk,
    const float* __restrict__ Wv)
{
    extern __shared__ float gsm[];
    float* As2 = gsm;
    float* Bs2 = gsm + 2 * 128 * AS_STRIDE;

    const int z = blockIdx.z;
    const float* W = (z == 0) ? Wq : ((z == 1) ? Wk : Wv);
    float* dst = (z == 0) ? g_Q : ((z == 1) ? g_K : g_V);

    const int tid = threadIdx.x;
    const int lane = tid & 31;
    const int warp = tid >> 5;
    const int wm = warp & 3;
    const int wn = warp >> 2;
    const int gid = lane >> 2;
    const int tig = lane & 3;
    const int s0 = blockIdx.y * 128;
    const int n0 = blockIdx.x * 64;
    const int head = blockIdx.x;

    float acc[2][4][4] = {};
    gemm_core_128x64(x, W, s0, n0, acc, As2, Bs2);

#pragma unroll
    for (int ma = 0; ma < 2; ma++) {
#pragma unroll
        for (int na = 0; na < 4; na++) {
#pragma unroll
            for (int rr = 0; rr < 2; rr++) {
                int row = s0 + wm * 32 + ma * 16 + gid + rr * 8;
                int d = wn * 32 + na * 8 + 2 * tig;
                float v0 = acc[ma][na][2 * rr + 0];
                float v1 = acc[ma][na][2 * rr + 1];
                float o0, o1;
                if (z < 2) {
                    float2 c = *(const float2*)&g_cos[row * HD + d];
                    float2 s = *(const float2*)&g_sin[row * HD + d];
                    o0 = v0 * c.x - v1 * s.x;
                    o1 = v1 * c.y + v0 * s.y;
                } else {
                    o0 = v0; o1 = v1;
                }
                *(float2*)&dst[(size_t)head * SEQ * HD + (size_t)row * HD + d] =
                    make_float2(o0, o1);
            }
        }
    }
}

// ---------------- output projection ----------------
__global__ void __launch_bounds__(256) oproj_kernel(
    const float* __restrict__ Wo, float* __restrict__ out)
{
    extern __shared__ float gsm[];
    float* As2 = gsm;
    float* Bs2 = gsm + 2 * 128 * AS_STRIDE;

    const int tid = threadIdx.x;
    const int lane = tid & 31;
    const int warp = tid >> 5;
    const int wm = warp & 3;
    const int wn = warp >> 2;
    const int gid = lane >> 2;
    const int tig = lane & 3;
    const int s0 = blockIdx.y * 128;
    const int n0 = blockIdx.x * 64;

    float acc[2][4][4] = {};
    gemm_core_128x64(g_ctx, Wo, s0, n0, acc, As2, Bs2);

#pragma unroll
    for (int ma = 0; ma < 2; ma++)
#pragma unroll
        for (int na = 0; na < 4; na++)
#pragma unroll
            for (int rr = 0; rr < 2; rr++) {
                int row = s0 + wm * 32 + ma * 16 + gid + rr * 8;
                int col = n0 + wn * 32 + na * 8 + 2 * tig;
                *(float2*)&out[(size_t)row * HDIM + col] =
                    make_float2(acc[ma][na][2 * rr + 0], acc[ma][na][2 * rr + 1]);
            }
}

// ---------------- flash attention (tf32 mma) ----------------
// grid (32 qblocks, 16 heads), 128 threads (4 warps x m32), k-tile 64.
// P transposed C-frag -> A-frag via register shuffles (no smem round trip).
// Tiles are 64 cols wide: QS/KS stride 68 (==4 mod 32), VS stride 72 (==8 mod 32).
#define QS_STRIDE 68
#define KS_STRIDE 68
#define VS_STRIDE 72
#define ATT_SMEM ((128 * QS_STRIDE + 64 * KS_STRIDE + 64 * VS_STRIDE + 64) * 4)

__global__ void __launch_bounds__(128) attn_kernel(const int* __restrict__ mask) {
    extern __shared__ unsigned sm_u[];
    unsigned* Qs = sm_u;
    unsigned* Ks = Qs + 128 * QS_STRIDE;
    unsigned* Vs = Ks + 64 * KS_STRIDE;
    float* sbias = (float*)(Vs + 64 * VS_STRIDE);

    const int tid = threadIdx.x;
    const int lane = tid & 31;
    const int w = tid >> 5;
    const int gid = lane >> 2;
    const int tig = lane & 3;
    const int q0 = blockIdx.x * 128;
    const int h = blockIdx.y;

    const float* Qg = g_Q + (size_t)h * SEQ * HD;
    const float* Kg = g_K + (size_t)h * SEQ * HD;
    const float* Vg = g_V + (size_t)h * SEQ * HD;

    // stage Q (tf32), once
#pragma unroll
    for (int i = 0; i < 16; i++) {
        int f = tid + 128 * i;
        int row = f >> 4;
        int c4 = (f & 15) * 4;
        float4 v = *(const float4*)&Qg[(size_t)(q0 + row) * HD + c4];
        *(uint4*)&Qs[row * QS_STRIDE + c4] =
            make_uint4(f2t(v.x), f2t(v.y), f2t(v.z), f2t(v.w));
    }

    float Oacc[2][8][4] = {};
    float mrow[4] = {-1e30f, -1e30f, -1e30f, -1e30f};
    float lrow[4] = {0.f, 0.f, 0.f, 0.f};
    const int qb = w * 32;

    for (int kt = 0; kt < SEQ / 64; kt++) {
        const int k0 = kt * 64;
        __syncthreads();
#pragma unroll
        for (int i = 0; i < 8; i++) {
            int f = tid + 128 * i;
            int row = f >> 4;
            int c4 = (f & 15) * 4;
            float4 kv = *(const float4*)&Kg[(size_t)(k0 + row) * HD + c4];
            *(uint4*)&Ks[row * KS_STRIDE + c4] =
                make_uint4(f2t(kv.x), f2t(kv.y), f2t(kv.z), f2t(kv.w));
            float4 vv = *(const float4*)&Vg[(size_t)(k0 + row) * HD + c4];
            *(uint4*)&Vs[row * VS_STRIDE + c4] =
                make_uint4(f2t(vv.x), f2t(vv.y), f2t(vv.z), f2t(vv.w));
        }
        if (tid < 64) sbias[tid] = (mask[k0 + tid] == 0) ? -1e30f : 0.f;
        __syncthreads();

        // ---- S = Q K^T ----
        float sacc[2][8][4] = {};
#pragma unroll
        for (int g = 0; g < 8; g++) {
            unsigned a0[4], a1[4];
            a0[0] = Qs[(qb + gid) * QS_STRIDE + g * 8 + tig];
            a0[1] = Qs[(qb + gid + 8) * QS_STRIDE + g * 8 + tig];
            a0[2] = Qs[(qb + gid) * QS_STRIDE + g * 8 + tig + 4];
            a0[3] = Qs[(qb + gid + 8) * QS_STRIDE + g * 8 + tig + 4];
            a1[0] = Qs[(qb + 16 + gid) * QS_STRIDE + g * 8 + tig];
            a1[1] = Qs[(qb + 16 + gid + 8) * QS_STRIDE + g * 8 + tig];
            a1[2] = Qs[(qb + 16 + gid) * QS_STRIDE + g * 8 + tig + 4];
            a1[3] = Qs[(qb + 16 + gid + 8) * QS_STRIDE + g * 8 + tig + 4];
#pragma unroll
            for (int na = 0; na < 8; na++) {
                unsigned b[2];
                int key = na * 8 + gid;
                b[0] = Ks[key * KS_STRIDE + g * 8 + tig];
                b[1] = Ks[key * KS_STRIDE + g * 8 + tig + 4];
                mma8(sacc[0][na], a0, b);
                mma8(sacc[1][na], a1, b);
            }
        }

        float bb[8][2];
#pragma unroll
        for (int na = 0; na < 8; na++) {
            bb[na][0] = sbias[na * 8 + 2 * tig];
            bb[na][1] = sbias[na * 8 + 2 * tig + 1];
        }

        // ---- online softmax ----
#pragma unroll
        for (int ma = 0; ma < 2; ma++) {
#pragma unroll
            for (int rr = 0; rr < 2; rr++) {
                const int li = ma * 2 + rr;
                float mt = -1e30f;
#pragma unroll
                for (int na = 0; na < 8; na++) {
#pragma unroll
                    for (int s = 0; s < 2; s++) {
                        float v = sacc[ma][na][2 * rr + s] * 0.125f + bb[na][s];
                        sacc[ma][na][2 * rr + s] = v;
                        mt = fmaxf(mt, v);
                    }
                }
                mt = fmaxf(mt, __shfl_xor_sync(0xffffffffu, mt, 1));
                mt = fmaxf(mt, __shfl_xor_sync(0xffffffffu, mt, 2));
                float mnew = fmaxf(mrow[li], mt);
                float corr = __expf(mrow[li] - mnew);
                float rs = 0.f;
#pragma unroll
                for (int na = 0; na < 8; na++) {
#pragma unroll
                    for (int s = 0; s < 2; s++) {
                        float p = __expf(sacc[ma][na][2 * rr + s] - mnew);
                        sacc[ma][na][2 * rr + s] = p;
                        rs += p;
                    }
                }
                rs += __shfl_xor_sync(0xffffffffu, rs, 1);
                rs += __shfl_xor_sync(0xffffffffu, rs, 2);
                lrow[li] = lrow[li] * corr + rs;
                mrow[li] = mnew;
#pragma unroll
                for (int nd = 0; nd < 8; nd++) {
                    Oacc[ma][nd][2 * rr + 0] *= corr;
                    Oacc[ma][nd][2 * rr + 1] *= corr;
                }
            }
        }

        // ---- O += P V : build P A-frags by shuffle-transpose of C-frags ----
        const int srcA = (lane & 0x1C) | (tig >> 1);
        const int srcB = srcA + 2;
        const bool odd = (tig & 1);
#pragma unroll
        for (int g = 0; g < 8; g++) {
            unsigned aP0[4], aP1[4];
            {
                float v0 = __shfl_sync(0xffffffffu, sacc[0][g][0], srcA);
                float v1 = __shfl_sync(0xffffffffu, sacc[0][g][1], srcA);
                float w0 = __shfl_sync(0xffffffffu, sacc[0][g][0], srcB);
                float w1 = __shfl_sync(0xffffffffu, sacc[0][g][1], srcB);
                float x0 = __shfl_sync(0xffffffffu, sacc[0][g][2], srcA);
                float x1 = __shfl_sync(0xffffffffu, sacc[0][g][3], srcA);
                float y0 = __shfl_sync(0xffffffffu, sacc[0][g][2], srcB);
                float y1 = __shfl_sync(0xffffffffu, sacc[0][g][3], srcB);
                aP0[0] = f2t(odd ? v1 : v0);
                aP0[2] = f2t(odd ? w1 : w0);
                aP0[1] = f2t(odd ? x1 : x0);
                aP0[3] = f2t(odd ? y1 : y0);
            }
            {
                float v0 = __shfl_sync(0xffffffffu, sacc[1][g][0], srcA);
                float v1 = __shfl_sync(0xffffffffu, sacc[1][g][1], srcA);
                float w0 = __shfl_sync(0xffffffffu, sacc[1][g][0], srcB);
                float w1 = __shfl_sync(0xffffffffu, sacc[1][g][1], srcB);
                float x0 = __shfl_sync(0xffffffffu, sacc[1][g][2], srcA);
                float x1 = __shfl_sync(0xffffffffu, sacc[1][g][3], srcA);
                float y0 = __shfl_sync(0xffffffffu, sacc[1][g][2], srcB);
                float y1 = __shfl_sync(0xffffffffu, sacc[1][g][3], srcB);
                aP1[0] = f2t(odd ? v1 : v0);
                aP1[2] = f2t(odd ? w1 : w0);
                aP1[1] = f2t(odd ? x1 : x0);
                aP1[3] = f2t(odd ? y1 : y0);
            }
#pragma unroll
            for (int nd = 0; nd < 8; nd++) {
                unsigned b[2];
                int d = nd * 8 + gid;
                b[0] = Vs[(g * 8 + tig) * VS_STRIDE + d];
                b[1] = Vs[(g * 8 + tig + 4) * VS_STRIDE + d];
                mma8(Oacc[0][nd], aP0, b);
                mma8(Oacc[1][nd], aP1, b);
            }
        }
    }

    // epilogue
    float inv[4];
#pragma unroll
    for (int i = 0; i < 4; i++) inv[i] = 1.0f / lrow[i];
#pragma unroll
    for (int ma = 0; ma < 2; ma++)
#pragma unroll
        for (int nd = 0; nd < 8; nd++)
#pragma unroll
            for (int rr = 0; rr < 2; rr++) {
                int row = q0 + qb + ma * 16 + gid + rr * 8;
                int d = nd * 8 + 2 * tig;
                float iv = inv[ma * 2 + rr];
                *(float2*)&g_ctx[(size_t)row * HDIM + h * HD + d] =
                    make_float2(Oacc[ma][nd][2 * rr] * iv, Oacc[ma][nd][2 * rr + 1] * iv);
            }
}

// ---------------- launch ----------------
extern "C" void kernel_launch(void* const* d_in, const int* in_sizes, int n_in,
                              void* d_out, int out_size) {
    const float* x  = (const float*)d_in[0];
    const float* Wq = (const float*)d_in[1];
    const float* Wk = (const float*)d_in[2];
    const float* Wv = (const float*)d_in[3];
    const float* Wo = (const float*)d_in[4];
    const int* mask = (const int*)d_in[5];
    float* out = (float*)d_out;

    cudaFuncSetAttribute(qkv_kernel,
                         cudaFuncAttributeMaxDynamicSharedMemorySize, GEMM_SMEM);
    cudaFuncSetAttribute(oproj_kernel,
                         cudaFuncAttributeMaxDynamicSharedMemorySize, GEMM_SMEM);
    cudaFuncSetAttribute(attn_kernel,
                         cudaFuncAttributeMaxDynamicSharedMemorySize, ATT_SMEM);

    rope_tables_kernel<<<(SEQ * HD + 255) / 256, 256>>>();
    qkv_kernel<<<dim3(NH, SEQ / 128, 3), 256, GEMM_SMEM>>>(x, Wq, Wk, Wv);
    attn_kernel<<<dim3(SEQ / 128, NH), 128, ATT_SMEM>>>(mask);
    oproj_kernel<<<dim3(HDIM / 64, SEQ / 128), 256, GEMM_SMEM>>>(Wo, out);
}

// round 6
// speedup vs baseline: 3.3235x; 1.0541x over previous
#include <cuda_runtime.h>
#include <math.h>

#define SEQ 4096
#define HDIM 1024
#define NH 16
#define HD 64

// ---------------- device scratch ----------------
__device__ float g_Q[NH * SEQ * HD];     // tf32-rounded
__device__ float g_K[NH * SEQ * HD];     // tf32-rounded
__device__ float g_V[NH * SEQ * HD];     // tf32-rounded
__device__ float g_ctx[SEQ * HDIM];      // tf32-rounded
__device__ float g_cos[SEQ * HD];
__device__ float g_sin[SEQ * HD];
__device__ float g_xt[SEQ * HDIM];       // tf32-rounded x
__device__ float g_Wqt[HDIM * HDIM];
__device__ float g_Wkt[HDIM * HDIM];
__device__ float g_Wvt[HDIM * HDIM];
__device__ float g_Wot[HDIM * HDIM];

// ---------------- helpers ----------------
__device__ __forceinline__ unsigned f2t(float f) {
    unsigned u;
    asm("cvt.rna.tf32.f32 %0, %1;" : "=r"(u) : "f"(f));
    return u;
}
__device__ __forceinline__ float f2tf(float f) { return __uint_as_float(f2t(f)); }

__device__ __forceinline__ void mma8(float* c, const unsigned* a, const unsigned* b) {
    asm volatile(
        "mma.sync.aligned.m16n8k8.row.col.f32.tf32.tf32.f32 "
        "{%0,%1,%2,%3}, {%4,%5,%6,%7}, {%8,%9}, {%0,%1,%2,%3};\n"
        : "+f"(c[0]), "+f"(c[1]), "+f"(c[2]), "+f"(c[3])
        : "r"(a[0]), "r"(a[1]), "r"(a[2]), "r"(a[3]), "r"(b[0]), "r"(b[1]));
}

__device__ __forceinline__ void cp16(unsigned dst, const void* src) {
    asm volatile("cp.async.cg.shared.global [%0], [%1], 16;" :: "r"(dst), "l"(src));
}
__device__ __forceinline__ void cp4(unsigned dst, const void* src) {
    asm volatile("cp.async.ca.shared.global [%0], [%1], 4;" :: "r"(dst), "l"(src));
}

// ---------------- prep: tf32-round x and weights ----------------
#define XN4 (SEQ * HDIM / 4)
#define WN4 (HDIM * HDIM / 4)
__global__ void preround_kernel(const float* __restrict__ x,
                                const float* __restrict__ Wq,
                                const float* __restrict__ Wk,
                                const float* __restrict__ Wv,
                                const float* __restrict__ Wo) {
    int i4 = blockIdx.x * 256 + threadIdx.x;
    const float* src;
    float* dst;
    int local;
    if (i4 < XN4) { src = x; dst = g_xt; local = i4; }
    else if (i4 < XN4 + WN4) { src = Wq; dst = g_Wqt; local = i4 - XN4; }
    else if (i4 < XN4 + 2 * WN4) { src = Wk; dst = g_Wkt; local = i4 - XN4 - WN4; }
    else if (i4 < XN4 + 3 * WN4) { src = Wv; dst = g_Wvt; local = i4 - XN4 - 2 * WN4; }
    else { src = Wo; dst = g_Wot; local = i4 - XN4 - 3 * WN4; }
    float4 v = ((const float4*)src)[local];
    v.x = f2tf(v.x); v.y = f2tf(v.y); v.z = f2tf(v.z); v.w = f2tf(v.w);
    ((float4*)dst)[local] = v;
}

// ---------------- RoPE tables ----------------
__global__ void rope_tables_kernel() {
    int idx = blockIdx.x * 256 + threadIdx.x;
    if (idx >= SEQ * HD) return;
    int t = idx >> 6;
    int j = idx & 63;
    int i = j & 31;
    float xe = (float)(2 * i) / 64.0f;
    float pf = (float)pow(10000.0, (double)xe);
    float invf = 1.0f / pf;
    float angf = (float)t * invf;
    double ang = (double)angf;
    g_cos[idx] = (float)cos(ang);
    g_sin[idx] = (float)sin(ang);
}

// ---------------- GEMM core (inputs pre-rounded: no cvt in mainloop) ----------------
#define AS_STRIDE 36
#define BS_STRIDE 72
#define GEMM_SMEM ((2 * 128 * AS_STRIDE + 2 * 32 * BS_STRIDE) * 4)

__device__ __forceinline__ void gemm_core_128x64(
    const float* __restrict__ A, const float* __restrict__ W,
    int s0, int n0, float acc[2][4][4], float* As2, float* Bs2)
{
    const int tid = threadIdx.x;
    const int lane = tid & 31;
    const int warp = tid >> 5;
    const int wm = warp & 3;
    const int wn = warp >> 2;
    const int gid = lane >> 2;
    const int tig = lane & 3;
    const int qb = wm * 32;

    unsigned asb = (unsigned)__cvta_generic_to_shared(As2);
    unsigned bsb = (unsigned)__cvta_generic_to_shared(Bs2);

    auto issue = [&](int k0, int buf) {
#pragma unroll
        for (int i = 0; i < 4; i++) {
            int f = tid + 256 * i;
            int row = f >> 3, c4 = (f & 7) * 4;
            cp16(asb + (unsigned)(buf * 128 * AS_STRIDE + row * AS_STRIDE + c4) * 4u,
                 &A[(size_t)(s0 + row) * HDIM + k0 + c4]);
        }
#pragma unroll
        for (int i = 0; i < 2; i++) {
            int f = tid + 256 * i;
            int row = f >> 4, c4 = (f & 15) * 4;
            cp16(bsb + (unsigned)(buf * 32 * BS_STRIDE + row * BS_STRIDE + c4) * 4u,
                 &W[(size_t)(k0 + row) * HDIM + n0 + c4]);
        }
    };

    issue(0, 0);
    asm volatile("cp.async.commit_group;");
    int buf = 0;

    for (int k0 = 0; k0 < HDIM; k0 += 32) {
        if (k0 + 32 < HDIM) {
            issue(k0 + 32, buf ^ 1);
            asm volatile("cp.async.commit_group;");
            asm volatile("cp.async.wait_group 1;");
        } else {
            asm volatile("cp.async.wait_group 0;");
        }
        __syncthreads();

        const unsigned* Af = (const unsigned*)As2 + buf * 128 * AS_STRIDE;
        const unsigned* Bf = (const unsigned*)Bs2 + buf * 32 * BS_STRIDE;
#pragma unroll
        for (int g = 0; g < 4; g++) {
            unsigned a0[4], a1[4];
            a0[0] = Af[(qb + gid) * AS_STRIDE + g * 8 + tig];
            a0[1] = Af[(qb + gid + 8) * AS_STRIDE + g * 8 + tig];
            a0[2] = Af[(qb + gid) * AS_STRIDE + g * 8 + tig + 4];
            a0[3] = Af[(qb + gid + 8) * AS_STRIDE + g * 8 + tig + 4];
            a1[0] = Af[(qb + 16 + gid) * AS_STRIDE + g * 8 + tig];
            a1[1] = Af[(qb + 16 + gid + 8) * AS_STRIDE + g * 8 + tig];
            a1[2] = Af[(qb + 16 + gid) * AS_STRIDE + g * 8 + tig + 4];
            a1[3] = Af[(qb + 16 + gid + 8) * AS_STRIDE + g * 8 + tig + 4];
#pragma unroll
            for (int na = 0; na < 4; na++) {
                unsigned b[2];
                int n = wn * 32 + na * 8 + gid;
                b[0] = Bf[(g * 8 + tig) * BS_STRIDE + n];
                b[1] = Bf[(g * 8 + tig + 4) * BS_STRIDE + n];
                mma8(acc[0][na], a0, b);
                mma8(acc[1][na], a1, b);
            }
        }
        buf ^= 1;
        __syncthreads();
    }
}

// ---------------- QKV projection + RoPE (writes tf32-rounded) ----------------
__global__ void __launch_bounds__(256) qkv_kernel() {
    extern __shared__ float gsm[];
    float* As2 = gsm;
    float* Bs2 = gsm + 2 * 128 * AS_STRIDE;

    const int z = blockIdx.z;
    const float* W = (z == 0) ? g_Wqt : ((z == 1) ? g_Wkt : g_Wvt);
    float* dst = (z == 0) ? g_Q : ((z == 1) ? g_K : g_V);

    const int tid = threadIdx.x;
    const int lane = tid & 31;
    const int warp = tid >> 5;
    const int wm = warp & 3;
    const int wn = warp >> 2;
    const int gid = lane >> 2;
    const int tig = lane & 3;
    const int s0 = blockIdx.y * 128;
    const int n0 = blockIdx.x * 64;
    const int head = blockIdx.x;

    float acc[2][4][4] = {};
    gemm_core_128x64(g_xt, W, s0, n0, acc, As2, Bs2);

#pragma unroll
    for (int ma = 0; ma < 2; ma++) {
#pragma unroll
        for (int na = 0; na < 4; na++) {
#pragma unroll
            for (int rr = 0; rr < 2; rr++) {
                int row = s0 + wm * 32 + ma * 16 + gid + rr * 8;
                int d = wn * 32 + na * 8 + 2 * tig;
                float v0 = acc[ma][na][2 * rr + 0];
                float v1 = acc[ma][na][2 * rr + 1];
                float o0, o1;
                if (z < 2) {
                    float2 c = *(const float2*)&g_cos[row * HD + d];
                    float2 s = *(const float2*)&g_sin[row * HD + d];
                    o0 = v0 * c.x - v1 * s.x;
                    o1 = v1 * c.y + v0 * s.y;
                } else {
                    o0 = v0; o1 = v1;
                }
                *(float2*)&dst[(size_t)head * SEQ * HD + (size_t)row * HD + d] =
                    make_float2(f2tf(o0), f2tf(o1));
            }
        }
    }
}

// ---------------- output projection ----------------
__global__ void __launch_bounds__(256) oproj_kernel(float* __restrict__ out) {
    extern __shared__ float gsm[];
    float* As2 = gsm;
    float* Bs2 = gsm + 2 * 128 * AS_STRIDE;

    const int tid = threadIdx.x;
    const int lane = tid & 31;
    const int warp = tid >> 5;
    const int wm = warp & 3;
    const int wn = warp >> 2;
    const int gid = lane >> 2;
    const int tig = lane & 3;
    const int s0 = blockIdx.y * 128;
    const int n0 = blockIdx.x * 64;

    float acc[2][4][4] = {};
    gemm_core_128x64(g_ctx, g_Wot, s0, n0, acc, As2, Bs2);

#pragma unroll
    for (int ma = 0; ma < 2; ma++)
#pragma unroll
        for (int na = 0; na < 4; na++)
#pragma unroll
            for (int rr = 0; rr < 2; rr++) {
                int row = s0 + wm * 32 + ma * 16 + gid + rr * 8;
                int col = n0 + wn * 32 + na * 8 + 2 * tig;
                *(float2*)&out[(size_t)row * HDIM + col] =
                    make_float2(acc[ma][na][2 * rr + 0], acc[ma][na][2 * rr + 1]);
            }
}

// ---------------- flash attention (tf32 mma, cp.async double-buffered K/V) ----------------
#define QS_STRIDE 68
#define KS_STRIDE 68
#define VS_STRIDE 72
#define ATT_SMEM ((128 * QS_STRIDE + 2 * 64 * KS_STRIDE + 2 * 64 * VS_STRIDE + 2 * 64) * 4)

__global__ void __launch_bounds__(128) attn_kernel(const int* __restrict__ mask) {
    extern __shared__ unsigned sm_u[];
    unsigned* Qs = sm_u;
    unsigned* Ks = Qs + 128 * QS_STRIDE;             // 2 x 64 x KS_STRIDE
    unsigned* Vs = Ks + 2 * 64 * KS_STRIDE;          // 2 x 64 x VS_STRIDE
    int* smask = (int*)(Vs + 2 * 64 * VS_STRIDE);    // 2 x 64

    const int tid = threadIdx.x;
    const int lane = tid & 31;
    const int w = tid >> 5;
    const int gid = lane >> 2;
    const int tig = lane & 3;
    const int q0 = blockIdx.x * 128;
    const int h = blockIdx.y;

    const float* Qg = g_Q + (size_t)h * SEQ * HD;
    const float* Kg = g_K + (size_t)h * SEQ * HD;
    const float* Vg = g_V + (size_t)h * SEQ * HD;

    unsigned ksb = (unsigned)__cvta_generic_to_shared(Ks);
    unsigned vsb = (unsigned)__cvta_generic_to_shared(Vs);
    unsigned msb = (unsigned)__cvta_generic_to_shared(smask);

    auto issue_kv = [&](int kt, int buf) {
        int k0 = kt * 64;
#pragma unroll
        for (int i = 0; i < 8; i++) {
            int f = tid + 128 * i;
            int row = f >> 4;
            int c4 = (f & 15) * 4;
            cp16(ksb + (unsigned)(buf * 64 * KS_STRIDE + row * KS_STRIDE + c4) * 4u,
                 &Kg[(size_t)(k0 + row) * HD + c4]);
            cp16(vsb + (unsigned)(buf * 64 * VS_STRIDE + row * VS_STRIDE + c4) * 4u,
                 &Vg[(size_t)(k0 + row) * HD + c4]);
        }
        if (tid < 64) cp4(msb + (unsigned)(buf * 64 + tid) * 4u, &mask[k0 + tid]);
    };

    // stage Q (already tf32-rounded)
#pragma unroll
    for (int i = 0; i < 16; i++) {
        int f = tid + 128 * i;
        int row = f >> 4;
        int c4 = (f & 15) * 4;
        *(uint4*)&Qs[row * QS_STRIDE + c4] =
            *(const uint4*)&Qg[(size_t)(q0 + row) * HD + c4];
    }

    float Oacc[2][8][4] = {};
    float mrow[4] = {-1e30f, -1e30f, -1e30f, -1e30f};
    float lrow[4] = {0.f, 0.f, 0.f, 0.f};
    const int qb = w * 32;

    issue_kv(0, 0);
    asm volatile("cp.async.commit_group;");
    int buf = 0;

    for (int kt = 0; kt < SEQ / 64; kt++) {
        if (kt + 1 < SEQ / 64) {
            issue_kv(kt + 1, buf ^ 1);
            asm volatile("cp.async.commit_group;");
            asm volatile("cp.async.wait_group 1;");
        } else {
            asm volatile("cp.async.wait_group 0;");
        }
        __syncthreads();

        const unsigned* Kf = Ks + buf * 64 * KS_STRIDE;
        const unsigned* Vf = Vs + buf * 64 * VS_STRIDE;
        const int* Mf = smask + buf * 64;

        // ---- S = Q K^T ----
        float sacc[2][8][4] = {};
#pragma unroll
        for (int g = 0; g < 8; g++) {
            unsigned a0[4], a1[4];
            a0[0] = Qs[(qb + gid) * QS_STRIDE + g * 8 + tig];
            a0[1] = Qs[(qb + gid + 8) * QS_STRIDE + g * 8 + tig];
            a0[2] = Qs[(qb + gid) * QS_STRIDE + g * 8 + tig + 4];
            a0[3] = Qs[(qb + gid + 8) * QS_STRIDE + g * 8 + tig + 4];
            a1[0] = Qs[(qb + 16 + gid) * QS_STRIDE + g * 8 + tig];
            a1[1] = Qs[(qb + 16 + gid + 8) * QS_STRIDE + g * 8 + tig];
            a1[2] = Qs[(qb + 16 + gid) * QS_STRIDE + g * 8 + tig + 4];
            a1[3] = Qs[(qb + 16 + gid + 8) * QS_STRIDE + g * 8 + tig + 4];
#pragma unroll
            for (int na = 0; na < 8; na++) {
                unsigned b[2];
                int key = na * 8 + gid;
                b[0] = Kf[key * KS_STRIDE + g * 8 + tig];
                b[1] = Kf[key * KS_STRIDE + g * 8 + tig + 4];
                mma8(sacc[0][na], a0, b);
                mma8(sacc[1][na], a1, b);
            }
        }

        float bb[8][2];
#pragma unroll
        for (int na = 0; na < 8; na++) {
            bb[na][0] = (Mf[na * 8 + 2 * tig] == 0) ? -1e30f : 0.f;
            bb[na][1] = (Mf[na * 8 + 2 * tig + 1] == 0) ? -1e30f : 0.f;
        }

        // ---- online softmax ----
#pragma unroll
        for (int ma = 0; ma < 2; ma++) {
#pragma unroll
            for (int rr = 0; rr < 2; rr++) {
                const int li = ma * 2 + rr;
                float mt = -1e30f;
#pragma unroll
                for (int na = 0; na < 8; na++) {
#pragma unroll
                    for (int s = 0; s < 2; s++) {
                        float v = sacc[ma][na][2 * rr + s] * 0.125f + bb[na][s];
                        sacc[ma][na][2 * rr + s] = v;
                        mt = fmaxf(mt, v);
                    }
                }
                mt = fmaxf(mt, __shfl_xor_sync(0xffffffffu, mt, 1));
                mt = fmaxf(mt, __shfl_xor_sync(0xffffffffu, mt, 2));
                float mnew = fmaxf(mrow[li], mt);
                float corr = __expf(mrow[li] - mnew);
                float rs = 0.f;
#pragma unroll
                for (int na = 0; na < 8; na++) {
#pragma unroll
                    for (int s = 0; s < 2; s++) {
                        float p = __expf(sacc[ma][na][2 * rr + s] - mnew);
                        sacc[ma][na][2 * rr + s] = p;
                        rs += p;
                    }
                }
                rs += __shfl_xor_sync(0xffffffffu, rs, 1);
                rs += __shfl_xor_sync(0xffffffffu, rs, 2);
                lrow[li] = lrow[li] * corr + rs;
                mrow[li] = mnew;
#pragma unroll
                for (int nd = 0; nd < 8; nd++) {
                    Oacc[ma][nd][2 * rr + 0] *= corr;
                    Oacc[ma][nd][2 * rr + 1] *= corr;
                }
            }
        }

        // ---- O += P V (shuffle-transpose C-frag -> A-frag) ----
        const int srcA = (lane & 0x1C) | (tig >> 1);
        const int srcB = srcA + 2;
        const bool odd = (tig & 1);
#pragma unroll
        for (int g = 0; g < 8; g++) {
            unsigned aP0[4], aP1[4];
            {
                float v0 = __shfl_sync(0xffffffffu, sacc[0][g][0], srcA);
                float v1 = __shfl_sync(0xffffffffu, sacc[0][g][1], srcA);
                float w0 = __shfl_sync(0xffffffffu, sacc[0][g][0], srcB);
                float w1 = __shfl_sync(0xffffffffu, sacc[0][g][1], srcB);
                float x0 = __shfl_sync(0xffffffffu, sacc[0][g][2], srcA);
                float x1 = __shfl_sync(0xffffffffu, sacc[0][g][3], srcA);
                float y0 = __shfl_sync(0xffffffffu, sacc[0][g][2], srcB);
                float y1 = __shfl_sync(0xffffffffu, sacc[0][g][3], srcB);
                aP0[0] = f2t(odd ? v1 : v0);
                aP0[2] = f2t(odd ? w1 : w0);
                aP0[1] = f2t(odd ? x1 : x0);
                aP0[3] = f2t(odd ? y1 : y0);
            }
            {
                float v0 = __shfl_sync(0xffffffffu, sacc[1][g][0], srcA);
                float v1 = __shfl_sync(0xffffffffu, sacc[1][g][1], srcA);
                float w0 = __shfl_sync(0xffffffffu, sacc[1][g][0], srcB);
                float w1 = __shfl_sync(0xffffffffu, sacc[1][g][1], srcB);
                float x0 = __shfl_sync(0xffffffffu, sacc[1][g][2], srcA);
                float x1 = __shfl_sync(0xffffffffu, sacc[1][g][3], srcA);
                float y0 = __shfl_sync(0xffffffffu, sacc[1][g][2], srcB);
                float y1 = __shfl_sync(0xffffffffu, sacc[1][g][3], srcB);
                aP1[0] = f2t(odd ? v1 : v0);
                aP1[2] = f2t(odd ? w1 : w0);
                aP1[1] = f2t(odd ? x1 : x0);
                aP1[3] = f2t(odd ? y1 : y0);
            }
#pragma unroll
            for (int nd = 0; nd < 8; nd++) {
                unsigned b[2];
                int d = nd * 8 + gid;
                b[0] = Vf[(g * 8 + tig) * VS_STRIDE + d];
                b[1] = Vf[(g * 8 + tig + 4) * VS_STRIDE + d];
                mma8(Oacc[0][nd], aP0, b);
                mma8(Oacc[1][nd], aP1, b);
            }
        }
        buf ^= 1;
        __syncthreads();
    }

    // epilogue: normalize, tf32-round, write ctx
    float inv[4];
#pragma unroll
    for (int i = 0; i < 4; i++) inv[i] = 1.0f / lrow[i];
#pragma unroll
    for (int ma = 0; ma < 2; ma++)
#pragma unroll
        for (int nd = 0; nd < 8; nd++)
#pragma unroll
            for (int rr = 0; rr < 2; rr++) {
                int row = q0 + qb + ma * 16 + gid + rr * 8;
                int d = nd * 8 + 2 * tig;
                float iv = inv[ma * 2 + rr];
                *(float2*)&g_ctx[(size_t)row * HDIM + h * HD + d] =
                    make_float2(f2tf(Oacc[ma][nd][2 * rr] * iv),
                                f2tf(Oacc[ma][nd][2 * rr + 1] * iv));
            }
}

// ---------------- launch ----------------
extern "C" void kernel_launch(void* const* d_in, const int* in_sizes, int n_in,
                              void* d_out, int out_size) {
    const float* x  = (const float*)d_in[0];
    const float* Wq = (const float*)d_in[1];
    const float* Wk = (const float*)d_in[2];
    const float* Wv = (const float*)d_in[3];
    const float* Wo = (const float*)d_in[4];
    const int* mask = (const int*)d_in[5];
    float* out = (float*)d_out;

    cudaFuncSetAttribute(qkv_kernel,
                         cudaFuncAttributeMaxDynamicSharedMemorySize, GEMM_SMEM);
    cudaFuncSetAttribute(oproj_kernel,
                         cudaFuncAttributeMaxDynamicSharedMemorySize, GEMM_SMEM);
    cudaFuncSetAttribute(attn_kernel,
                         cudaFuncAttributeMaxDynamicSharedMemorySize, ATT_SMEM);

    preround_kernel<<<(XN4 + 4 * WN4) / 256, 256>>>(x, Wq, Wk, Wv, Wo);
    rope_tables_kernel<<<(SEQ * HD + 255) / 256, 256>>>();
    qkv_kernel<<<dim3(NH, SEQ / 128, 3), 256, GEMM_SMEM>>>();
    attn_kernel<<<dim3(SEQ / 128, NH), 128, ATT_SMEM>>>(mask);
    oproj_kernel<<<dim3(HDIM / 64, SEQ / 128), 256, GEMM_SMEM>>>(out);
}

// round 7
// speedup vs baseline: 3.3685x; 1.0136x over previous
#include <cuda_runtime.h>
#include <math.h>

#define SEQ 4096
#define HDIM 1024
#define NH 16
#define HD 64

// ---------------- device scratch ----------------
__device__ float g_Q[NH * SEQ * HD];     // tf32-rounded, pre-scaled by 0.125
__device__ float g_K[NH * SEQ * HD];     // tf32-rounded
__device__ float g_V[NH * SEQ * HD];     // tf32-rounded
__device__ float g_ctx[SEQ * HDIM];      // tf32-rounded
__device__ float g_cos[SEQ * HD];
__device__ float g_sin[SEQ * HD];
__device__ float g_xt[SEQ * HDIM];       // tf32-rounded x
__device__ float g_Wqt[HDIM * HDIM];
__device__ float g_Wkt[HDIM * HDIM];
__device__ float g_Wvt[HDIM * HDIM];
__device__ float g_Wot[HDIM * HDIM];

// ---------------- helpers ----------------
__device__ __forceinline__ unsigned f2t(float f) {
    unsigned u;
    asm("cvt.rna.tf32.f32 %0, %1;" : "=r"(u) : "f"(f));
    return u;
}
__device__ __forceinline__ float f2tf(float f) { return __uint_as_float(f2t(f)); }

__device__ __forceinline__ void mma8(float* c, const unsigned* a, const unsigned* b) {
    asm volatile(
        "mma.sync.aligned.m16n8k8.row.col.f32.tf32.tf32.f32 "
        "{%0,%1,%2,%3}, {%4,%5,%6,%7}, {%8,%9}, {%0,%1,%2,%3};\n"
        : "+f"(c[0]), "+f"(c[1]), "+f"(c[2]), "+f"(c[3])
        : "r"(a[0]), "r"(a[1]), "r"(a[2]), "r"(a[3]), "r"(b[0]), "r"(b[1]));
}

__device__ __forceinline__ void cp16(unsigned dst, const void* src) {
    asm volatile("cp.async.cg.shared.global [%0], [%1], 16;" :: "r"(dst), "l"(src));
}
__device__ __forceinline__ void cp4(unsigned dst, const void* src) {
    asm volatile("cp.async.ca.shared.global [%0], [%1], 4;" :: "r"(dst), "l"(src));
}

// ---------------- prep: tf32-round x and weights ----------------
#define XN4 (SEQ * HDIM / 4)
#define WN4 (HDIM * HDIM / 4)
__global__ void preround_kernel(const float* __restrict__ x,
                                const float* __restrict__ Wq,
                                const float* __restrict__ Wk,
                                const float* __restrict__ Wv,
                                const float* __restrict__ Wo) {
    int i4 = blockIdx.x * 256 + threadIdx.x;
    const float* src;
    float* dst;
    int local;
    if (i4 < XN4) { src = x; dst = g_xt; local = i4; }
    else if (i4 < XN4 + WN4) { src = Wq; dst = g_Wqt; local = i4 - XN4; }
    else if (i4 < XN4 + 2 * WN4) { src = Wk; dst = g_Wkt; local = i4 - XN4 - WN4; }
    else if (i4 < XN4 + 3 * WN4) { src = Wv; dst = g_Wvt; local = i4 - XN4 - 2 * WN4; }
    else { src = Wo; dst = g_Wot; local = i4 - XN4 - 3 * WN4; }
    float4 v = ((const float4*)src)[local];
    v.x = f2tf(v.x); v.y = f2tf(v.y); v.z = f2tf(v.z); v.w = f2tf(v.w);
    ((float4*)dst)[local] = v;
}

// ---------------- RoPE tables ----------------
__global__ void rope_tables_kernel() {
    int idx = blockIdx.x * 256 + threadIdx.x;
    if (idx >= SEQ * HD) return;
    int t = idx >> 6;
    int j = idx & 63;
    int i = j & 31;
    float xe = (float)(2 * i) / 64.0f;
    float pf = (float)pow(10000.0, (double)xe);
    float invf = 1.0f / pf;
    float angf = (float)t * invf;
    double ang = (double)angf;
    g_cos[idx] = (float)cos(ang);
    g_sin[idx] = (float)sin(ang);
}

// ---------------- GEMM core (inputs pre-rounded: no cvt in mainloop) ----------------
#define AS_STRIDE 36
#define BS_STRIDE 72
#define GEMM_SMEM ((2 * 128 * AS_STRIDE + 2 * 32 * BS_STRIDE) * 4)

__device__ __forceinline__ void gemm_core_128x64(
    const float* __restrict__ A, const float* __restrict__ W,
    int s0, int n0, float acc[2][4][4], float* As2, float* Bs2)
{
    const int tid = threadIdx.x;
    const int lane = tid & 31;
    const int warp = tid >> 5;
    const int wm = warp & 3;
    const int wn = warp >> 2;
    const int gid = lane >> 2;
    const int tig = lane & 3;
    const int qb = wm * 32;

    unsigned asb = (unsigned)__cvta_generic_to_shared(As2);
    unsigned bsb = (unsigned)__cvta_generic_to_shared(Bs2);

    auto issue = [&](int k0, int buf) {
#pragma unroll
        for (int i = 0; i < 4; i++) {
            int f = tid + 256 * i;
            int row = f >> 3, c4 = (f & 7) * 4;
            cp16(asb + (unsigned)(buf * 128 * AS_STRIDE + row * AS_STRIDE + c4) * 4u,
                 &A[(size_t)(s0 + row) * HDIM + k0 + c4]);
        }
#pragma unroll
        for (int i = 0; i < 2; i++) {
            int f = tid + 256 * i;
            int row = f >> 4, c4 = (f & 15) * 4;
            cp16(bsb + (unsigned)(buf * 32 * BS_STRIDE + row * BS_STRIDE + c4) * 4u,
                 &W[(size_t)(k0 + row) * HDIM + n0 + c4]);
        }
    };

    issue(0, 0);
    asm volatile("cp.async.commit_group;");
    int buf = 0;

    for (int k0 = 0; k0 < HDIM; k0 += 32) {
        if (k0 + 32 < HDIM) {
            issue(k0 + 32, buf ^ 1);
            asm volatile("cp.async.commit_group;");
            asm volatile("cp.async.wait_group 1;");
        } else {
            asm volatile("cp.async.wait_group 0;");
        }
        __syncthreads();

        const unsigned* Af = (const unsigned*)As2 + buf * 128 * AS_STRIDE;
        const unsigned* Bf = (const unsigned*)Bs2 + buf * 32 * BS_STRIDE;
#pragma unroll
        for (int g = 0; g < 4; g++) {
            unsigned a0[4], a1[4];
            a0[0] = Af[(qb + gid) * AS_STRIDE + g * 8 + tig];
            a0[1] = Af[(qb + gid + 8) * AS_STRIDE + g * 8 + tig];
            a0[2] = Af[(qb + gid) * AS_STRIDE + g * 8 + tig + 4];
            a0[3] = Af[(qb + gid + 8) * AS_STRIDE + g * 8 + tig + 4];
            a1[0] = Af[(qb + 16 + gid) * AS_STRIDE + g * 8 + tig];
            a1[1] = Af[(qb + 16 + gid + 8) * AS_STRIDE + g * 8 + tig];
            a1[2] = Af[(qb + 16 + gid) * AS_STRIDE + g * 8 + tig + 4];
            a1[3] = Af[(qb + 16 + gid + 8) * AS_STRIDE + g * 8 + tig + 4];
#pragma unroll
            for (int na = 0; na < 4; na++) {
                unsigned b[2];
                int n = wn * 32 + na * 8 + gid;
                b[0] = Bf[(g * 8 + tig) * BS_STRIDE + n];
                b[1] = Bf[(g * 8 + tig + 4) * BS_STRIDE + n];
                mma8(acc[0][na], a0, b);
                mma8(acc[1][na], a1, b);
            }
        }
        buf ^= 1;
        __syncthreads();
    }
}

// ---------------- QKV projection + RoPE (writes tf32-rounded; Q pre-scaled) ----------------
__global__ void __launch_bounds__(256) qkv_kernel() {
    extern __shared__ float gsm[];
    float* As2 = gsm;
    float* Bs2 = gsm + 2 * 128 * AS_STRIDE;

    const int z = blockIdx.z;
    const float* W = (z == 0) ? g_Wqt : ((z == 1) ? g_Wkt : g_Wvt);
    float* dst = (z == 0) ? g_Q : ((z == 1) ? g_K : g_V);

    const int tid = threadIdx.x;
    const int lane = tid & 31;
    const int warp = tid >> 5;
    const int wm = warp & 3;
    const int wn = warp >> 2;
    const int gid = lane >> 2;
    const int tig = lane & 3;
    const int s0 = blockIdx.y * 128;
    const int n0 = blockIdx.x * 64;
    const int head = blockIdx.x;
    const float qscale = (z == 0) ? 0.125f : 1.0f;   // exact pow2: fold 1/sqrt(hd) into Q

    float acc[2][4][4] = {};
    gemm_core_128x64(g_xt, W, s0, n0, acc, As2, Bs2);

#pragma unroll
    for (int ma = 0; ma < 2; ma++) {
#pragma unroll
        for (int na = 0; na < 4; na++) {
#pragma unroll
            for (int rr = 0; rr < 2; rr++) {
                int row = s0 + wm * 32 + ma * 16 + gid + rr * 8;
                int d = wn * 32 + na * 8 + 2 * tig;
                float v0 = acc[ma][na][2 * rr + 0];
                float v1 = acc[ma][na][2 * rr + 1];
                float o0, o1;
                if (z < 2) {
                    float2 c = *(const float2*)&g_cos[row * HD + d];
                    float2 s = *(const float2*)&g_sin[row * HD + d];
                    o0 = (v0 * c.x - v1 * s.x) * qscale;
                    o1 = (v1 * c.y + v0 * s.y) * qscale;
                } else {
                    o0 = v0; o1 = v1;
                }
                *(float2*)&dst[(size_t)head * SEQ * HD + (size_t)row * HD + d] =
                    make_float2(f2tf(o0), f2tf(o1));
            }
        }
    }
}

// ---------------- output projection ----------------
__global__ void __launch_bounds__(256) oproj_kernel(float* __restrict__ out) {
    extern __shared__ float gsm[];
    float* As2 = gsm;
    float* Bs2 = gsm + 2 * 128 * AS_STRIDE;

    const int tid = threadIdx.x;
    const int lane = tid & 31;
    const int warp = tid >> 5;
    const int wm = warp & 3;
    const int wn = warp >> 2;
    const int gid = lane >> 2;
    const int tig = lane & 3;
    const int s0 = blockIdx.y * 128;
    const int n0 = blockIdx.x * 64;

    float acc[2][4][4] = {};
    gemm_core_128x64(g_ctx, g_Wot, s0, n0, acc, As2, Bs2);

#pragma unroll
    for (int ma = 0; ma < 2; ma++)
#pragma unroll
        for (int na = 0; na < 4; na++)
#pragma unroll
            for (int rr = 0; rr < 2; rr++) {
                int row = s0 + wm * 32 + ma * 16 + gid + rr * 8;
                int col = n0 + wn * 32 + na * 8 + 2 * tig;
                *(float2*)&out[(size_t)row * HDIM + col] =
                    make_float2(acc[ma][na][2 * rr + 0], acc[ma][na][2 * rr + 1]);
            }
}

// ---------------- flash attention: 8 warps x m16, 2 CTAs/SM ----------------
#define QS_STRIDE 68
#define KS_STRIDE 68
#define VS_STRIDE 72
#define ATT_SMEM ((128 * QS_STRIDE + 2 * 64 * KS_STRIDE + 2 * 64 * VS_STRIDE + 2 * 64) * 4)

__global__ void __launch_bounds__(256, 2) attn_kernel(const int* __restrict__ mask) {
    extern __shared__ unsigned sm_u[];
    unsigned* Qs = sm_u;
    unsigned* Ks = Qs + 128 * QS_STRIDE;             // 2 x 64 x KS_STRIDE
    unsigned* Vs = Ks + 2 * 64 * KS_STRIDE;          // 2 x 64 x VS_STRIDE
    int* smask = (int*)(Vs + 2 * 64 * VS_STRIDE);    // 2 x 64

    const int tid = threadIdx.x;
    const int lane = tid & 31;
    const int w = tid >> 5;                           // 0..7
    const int gid = lane >> 2;
    const int tig = lane & 3;
    const int q0 = blockIdx.x * 128;
    const int h = blockIdx.y;
    const int qb = w * 16;                            // warp owns 16 q-rows

    const float* Qg = g_Q + (size_t)h * SEQ * HD;
    const float* Kg = g_K + (size_t)h * SEQ * HD;
    const float* Vg = g_V + (size_t)h * SEQ * HD;

    unsigned ksb = (unsigned)__cvta_generic_to_shared(Ks);
    unsigned vsb = (unsigned)__cvta_generic_to_shared(Vs);
    unsigned msb = (unsigned)__cvta_generic_to_shared(smask);

    auto issue_kv = [&](int kt, int buf) {
        int k0 = kt * 64;
#pragma unroll
        for (int i = 0; i < 4; i++) {
            int f = tid + 256 * i;
            int row = f >> 4;
            int c4 = (f & 15) * 4;
            cp16(ksb + (unsigned)(buf * 64 * KS_STRIDE + row * KS_STRIDE + c4) * 4u,
                 &Kg[(size_t)(k0 + row) * HD + c4]);
            cp16(vsb + (unsigned)(buf * 64 * VS_STRIDE + row * VS_STRIDE + c4) * 4u,
                 &Vg[(size_t)(k0 + row) * HD + c4]);
        }
        if (tid < 64) cp4(msb + (unsigned)(buf * 64 + tid) * 4u, &mask[k0 + tid]);
    };

    // stage Q (already tf32-rounded + pre-scaled)
#pragma unroll
    for (int i = 0; i < 8; i++) {
        int f = tid + 256 * i;
        int row = f >> 4;
        int c4 = (f & 15) * 4;
        *(uint4*)&Qs[row * QS_STRIDE + c4] =
            *(const uint4*)&Qg[(size_t)(q0 + row) * HD + c4];
    }

    float Oacc[8][4] = {};
    float mrow[2] = {-1e30f, -1e30f};
    float lrow[2] = {0.f, 0.f};

    issue_kv(0, 0);
    asm volatile("cp.async.commit_group;");
    int buf = 0;

    for (int kt = 0; kt < SEQ / 64; kt++) {
        if (kt + 1 < SEQ / 64) {
            issue_kv(kt + 1, buf ^ 1);
            asm volatile("cp.async.commit_group;");
            asm volatile("cp.async.wait_group 1;");
        } else {
            asm volatile("cp.async.wait_group 0;");
        }
        __syncthreads();

        const unsigned* Kf = Ks + buf * 64 * KS_STRIDE;
        const unsigned* Vf = Vs + buf * 64 * VS_STRIDE;
        const int* Mf = smask + buf * 64;

        // ---- S = Q K^T (scale pre-folded into Q) ----
        float sacc[8][4] = {};
#pragma unroll
        for (int g = 0; g < 8; g++) {
            unsigned a[4];
            a[0] = Qs[(qb + gid) * QS_STRIDE + g * 8 + tig];
            a[1] = Qs[(qb + gid + 8) * QS_STRIDE + g * 8 + tig];
            a[2] = Qs[(qb + gid) * QS_STRIDE + g * 8 + tig + 4];
            a[3] = Qs[(qb + gid + 8) * QS_STRIDE + g * 8 + tig + 4];
#pragma unroll
            for (int na = 0; na < 8; na++) {
                unsigned b[2];
                int key = na * 8 + gid;
                b[0] = Kf[key * KS_STRIDE + g * 8 + tig];
                b[1] = Kf[key * KS_STRIDE + g * 8 + tig + 4];
                mma8(sacc[na], a, b);
            }
        }

        // ---- mask bias (skipped when tile has no zeros) ----
        bool localz = false;
        float bb[8][2];
#pragma unroll
        for (int na = 0; na < 8; na++) {
            int m0 = Mf[na * 8 + 2 * tig];
            int m1 = Mf[na * 8 + 2 * tig + 1];
            bb[na][0] = (m0 == 0) ? -1e30f : 0.f;
            bb[na][1] = (m1 == 0) ? -1e30f : 0.f;
            localz |= (m0 == 0) | (m1 == 0);
        }
        if (__any_sync(0xffffffffu, localz)) {
#pragma unroll
            for (int na = 0; na < 8; na++)
#pragma unroll
                for (int rr = 0; rr < 2; rr++) {
                    sacc[na][2 * rr + 0] += bb[na][0];
                    sacc[na][2 * rr + 1] += bb[na][1];
                }
        }

        // ---- online softmax (2 rows per thread: gid, gid+8) ----
#pragma unroll
        for (int rr = 0; rr < 2; rr++) {
            float mt = -1e30f;
#pragma unroll
            for (int na = 0; na < 8; na++) {
                mt = fmaxf(mt, fmaxf(sacc[na][2 * rr], sacc[na][2 * rr + 1]));
            }
            mt = fmaxf(mt, __shfl_xor_sync(0xffffffffu, mt, 1));
            mt = fmaxf(mt, __shfl_xor_sync(0xffffffffu, mt, 2));
            float mnew = fmaxf(mrow[rr], mt);
            float corr = __expf(mrow[rr] - mnew);
            float rs = 0.f;
#pragma unroll
            for (int na = 0; na < 8; na++) {
#pragma unroll
                for (int s = 0; s < 2; s++) {
                    float p = __expf(sacc[na][2 * rr + s] - mnew);
                    sacc[na][2 * rr + s] = p;
                    rs += p;
                }
            }
            rs += __shfl_xor_sync(0xffffffffu, rs, 1);
            rs += __shfl_xor_sync(0xffffffffu, rs, 2);
            lrow[rr] = lrow[rr] * corr + rs;
            mrow[rr] = mnew;
#pragma unroll
            for (int nd = 0; nd < 8; nd++) {
                Oacc[nd][2 * rr + 0] *= corr;
                Oacc[nd][2 * rr + 1] *= corr;
            }
        }

        // ---- O += P V (shuffle-transpose C-frag -> A-frag) ----
        const int srcA = (lane & 0x1C) | (tig >> 1);
        const int srcB = srcA + 2;
        const bool odd = (tig & 1);
#pragma unroll
        for (int g = 0; g < 8; g++) {
            unsigned aP[4];
            {
                float v0 = __shfl_sync(0xffffffffu, sacc[g][0], srcA);
                float v1 = __shfl_sync(0xffffffffu, sacc[g][1], srcA);
                float w0 = __shfl_sync(0xffffffffu, sacc[g][0], srcB);
                float w1 = __shfl_sync(0xffffffffu, sacc[g][1], srcB);
                float x0 = __shfl_sync(0xffffffffu, sacc[g][2], srcA);
                float x1 = __shfl_sync(0xffffffffu, sacc[g][3], srcA);
                float y0 = __shfl_sync(0xffffffffu, sacc[g][2], srcB);
                float y1 = __shfl_sync(0xffffffffu, sacc[g][3], srcB);
                aP[0] = f2t(odd ? v1 : v0);
                aP[2] = f2t(odd ? w1 : w0);
                aP[1] = f2t(odd ? x1 : x0);
                aP[3] = f2t(odd ? y1 : y0);
            }
#pragma unroll
            for (int nd = 0; nd < 8; nd++) {
                unsigned b[2];
                int d = nd * 8 + gid;
                b[0] = Vf[(g * 8 + tig) * VS_STRIDE + d];
                b[1] = Vf[(g * 8 + tig + 4) * VS_STRIDE + d];
                mma8(Oacc[nd], aP, b);
            }
        }
        buf ^= 1;
        __syncthreads();
    }

    // epilogue: normalize, tf32-round, write ctx
    float inv[2] = {1.0f / lrow[0], 1.0f / lrow[1]};
#pragma unroll
    for (int nd = 0; nd < 8; nd++)
#pragma unroll
        for (int rr = 0; rr < 2; rr++) {
            int row = q0 + qb + gid + rr * 8;
            int d = nd * 8 + 2 * tig;
            float iv = inv[rr];
            *(float2*)&g_ctx[(size_t)row * HDIM + h * HD + d] =
                make_float2(f2tf(Oacc[nd][2 * rr] * iv),
                            f2tf(Oacc[nd][2 * rr + 1] * iv));
        }
}

// ---------------- launch ----------------
extern "C" void kernel_launch(void* const* d_in, const int* in_sizes, int n_in,
                              void* d_out, int out_size) {
    const float* x  = (const float*)d_in[0];
    const float* Wq = (const float*)d_in[1];
    const float* Wk = (const float*)d_in[2];
    const float* Wv = (const float*)d_in[3];
    const float* Wo = (const float*)d_in[4];
    const int* mask = (const int*)d_in[5];
    float* out = (float*)d_out;

    cudaFuncSetAttribute(qkv_kernel,
                         cudaFuncAttributeMaxDynamicSharedMemorySize, GEMM_SMEM);
    cudaFuncSetAttribute(oproj_kernel,
                         cudaFuncAttributeMaxDynamicSharedMemorySize, GEMM_SMEM);
    cudaFuncSetAttribute(attn_kernel,
                         cudaFuncAttributeMaxDynamicSharedMemorySize, ATT_SMEM);

    preround_kernel<<<(XN4 + 4 * WN4) / 256, 256>>>(x, Wq, Wk, Wv, Wo);
    rope_tables_kernel<<<(SEQ * HD + 255) / 256, 256>>>();
    qkv_kernel<<<dim3(NH, SEQ / 128, 3), 256, GEMM_SMEM>>>();
    attn_kernel<<<dim3(SEQ / 128, NH), 256, ATT_SMEM>>>(mask);
    oproj_kernel<<<dim3(HDIM / 64, SEQ / 128), 256, GEMM_SMEM>>>(out);
}

// round 8
// speedup vs baseline: 5.7249x; 1.6995x over previous
#include <cuda_runtime.h>
#include <cuda_fp16.h>
#include <math.h>

#define SEQ 4096
#define HDIM 1024
#define NH 16
#define HD 64
#define WSTR 36   // smem word stride (36 words = 72 halves) for 64-half-wide rows

// ---------------- device scratch (fp16 operands, fp32 tables) ----------------
__device__ __half g_Qh[NH * SEQ * HD];    // [h][s][d], pre-scaled by 0.125
__device__ __half g_Kh[NH * SEQ * HD];    // [h][s][d]
__device__ __half g_Vh[NH * SEQ * HD];    // [h][d][s]  TRANSPOSED
__device__ __half g_ctxh[SEQ * HDIM];     // [s][h*64+d]
__device__ __half g_xh[SEQ * HDIM];
__device__ __half g_Wqh[HDIM * HDIM];     // transposed [n][k]
__device__ __half g_Wkh[HDIM * HDIM];
__device__ __half g_Wvh[HDIM * HDIM];
__device__ __half g_Woh[HDIM * HDIM];
__device__ float g_cos[SEQ * HD];
__device__ float g_sin[SEQ * HD];

// ---------------- helpers ----------------
__device__ __forceinline__ void mma16(float* c, const unsigned* a, const unsigned* b) {
    asm volatile(
        "mma.sync.aligned.m16n8k16.row.col.f32.f16.f16.f32 "
        "{%0,%1,%2,%3}, {%4,%5,%6,%7}, {%8,%9}, {%0,%1,%2,%3};\n"
        : "+f"(c[0]), "+f"(c[1]), "+f"(c[2]), "+f"(c[3])
        : "r"(a[0]), "r"(a[1]), "r"(a[2]), "r"(a[3]), "r"(b[0]), "r"(b[1]));
}

__device__ __forceinline__ unsigned packh2(float lo, float hi) {
    __half2 h = __floats2half2_rn(lo, hi);   // x=lo, y=hi
    return *(unsigned*)&h;
}

__device__ __forceinline__ void cp16(unsigned dst, const void* src) {
    asm volatile("cp.async.cg.shared.global [%0], [%1], 16;" :: "r"(dst), "l"(src));
}
__device__ __forceinline__ void cp4(unsigned dst, const void* src) {
    asm volatile("cp.async.ca.shared.global [%0], [%1], 4;" :: "r"(dst), "l"(src));
}

// ---------------- prep kernels ----------------
__global__ void x2h_kernel(const float* __restrict__ x) {
    int i = blockIdx.x * 256 + threadIdx.x;       // indexes float4
    float4 v = ((const float4*)x)[i];
    uint2 u;
    u.x = packh2(v.x, v.y);
    u.y = packh2(v.z, v.w);
    ((uint2*)g_xh)[i] = u;
}

// Transpose W [k][n] fp32 -> Wt [n][k] fp16 (one-time).
__global__ void wtrans_kernel(const float* __restrict__ Wq,
                              const float* __restrict__ Wk,
                              const float* __restrict__ Wv,
                              const float* __restrict__ Wo) {
    __shared__ float tile[64][65];
    const int z = blockIdx.z;
    const float* W = (z == 0) ? Wq : (z == 1) ? Wk : (z == 2) ? Wv : Wo;
    __half* Wt = (z == 0) ? g_Wqh : (z == 1) ? g_Wkh : (z == 2) ? g_Wvh : g_Woh;
    const int k0 = blockIdx.x * 64, n0 = blockIdx.y * 64;
    const int tid = threadIdx.x;
#pragma unroll
    for (int i = 0; i < 16; i++) {
        int idx = tid + 256 * i;
        int r = idx >> 6, c = idx & 63;
        tile[r][c] = W[(size_t)(k0 + r) * HDIM + n0 + c];
    }
    __syncthreads();
#pragma unroll
    for (int i = 0; i < 16; i++) {
        int idx = tid + 256 * i;
        int r = idx >> 6, c = idx & 63;
        Wt[(size_t)(n0 + r) * HDIM + k0 + c] = __float2half_rn(tile[c][r]);
    }
}

// ---------------- RoPE tables ----------------
__global__ void rope_tables_kernel() {
    int idx = blockIdx.x * 256 + threadIdx.x;
    if (idx >= SEQ * HD) return;
    int t = idx >> 6;
    int j = idx & 63;
    int i = j & 31;
    float xe = (float)(2 * i) / 64.0f;
    float pf = (float)pow(10000.0, (double)xe);
    float invf = 1.0f / pf;
    float angf = (float)t * invf;
    double ang = (double)angf;
    g_cos[idx] = (float)cos(ang);
    g_sin[idx] = (float)sin(ang);
}

// ---------------- fp16 GEMM core: C[128x64] = A[128,1024] @ Wt^T ----------------
// 8 warps (4M x 2N), warp m32 x n32, k-step 64 (4 x k16 mma groups), double-buffered.
#define GEMM_SMEM ((2 * 128 * WSTR + 2 * 64 * WSTR) * 4)

__device__ __forceinline__ void gemm_core_128x64(
    const __half* __restrict__ A, const __half* __restrict__ Wt,
    int s0, int n0, float acc[2][4][4], unsigned* As, unsigned* Ws)
{
    const int tid = threadIdx.x;
    const int lane = tid & 31;
    const int warp = tid >> 5;
    const int wm = warp & 3;
    const int wn = warp >> 2;
    const int gid = lane >> 2;
    const int tig = lane & 3;
    const int qb = wm * 32;

    unsigned asb = (unsigned)__cvta_generic_to_shared(As);
    unsigned bsb = (unsigned)__cvta_generic_to_shared(Ws);

    auto issue = [&](int k0, int buf) {
#pragma unroll
        for (int i = 0; i < 4; i++) {           // A: 128 rows x 8 chunks of 8 halves
            int f = tid + 256 * i;
            int row = f >> 3, ch = f & 7;
            cp16(asb + (unsigned)(buf * 128 * WSTR + row * WSTR + ch * 4) * 4u,
                 &A[(size_t)(s0 + row) * HDIM + k0 + ch * 8]);
        }
#pragma unroll
        for (int i = 0; i < 2; i++) {           // Wt: 64 rows x 8 chunks
            int f = tid + 256 * i;
            int row = f >> 3, ch = f & 7;
            cp16(bsb + (unsigned)(buf * 64 * WSTR + row * WSTR + ch * 4) * 4u,
                 &Wt[(size_t)(n0 + row) * HDIM + k0 + ch * 8]);
        }
    };

    issue(0, 0);
    asm volatile("cp.async.commit_group;");
    int buf = 0;

    for (int k0 = 0; k0 < HDIM; k0 += 64) {
        if (k0 + 64 < HDIM) {
            issue(k0 + 64, buf ^ 1);
            asm volatile("cp.async.commit_group;");
            asm volatile("cp.async.wait_group 1;");
        } else {
            asm volatile("cp.async.wait_group 0;");
        }
        __syncthreads();

        const unsigned* Af = As + buf * 128 * WSTR;
        const unsigned* Bf = Ws + buf * 64 * WSTR;
#pragma unroll
        for (int kg = 0; kg < 4; kg++) {
            unsigned a0[4], a1[4];
            a0[0] = Af[(qb + gid) * WSTR + kg * 8 + tig];
            a0[1] = Af[(qb + gid + 8) * WSTR + kg * 8 + tig];
            a0[2] = Af[(qb + gid) * WSTR + kg * 8 + tig + 4];
            a0[3] = Af[(qb + gid + 8) * WSTR + kg * 8 + tig + 4];
            a1[0] = Af[(qb + 16 + gid) * WSTR + kg * 8 + tig];
            a1[1] = Af[(qb + 16 + gid + 8) * WSTR + kg * 8 + tig];
            a1[2] = Af[(qb + 16 + gid) * WSTR + kg * 8 + tig + 4];
            a1[3] = Af[(qb + 16 + gid + 8) * WSTR + kg * 8 + tig + 4];
#pragma unroll
            for (int na = 0; na < 4; na++) {
                unsigned b[2];
                int n = wn * 32 + na * 8 + gid;
                b[0] = Bf[n * WSTR + kg * 8 + tig];
                b[1] = Bf[n * WSTR + kg * 8 + tig + 4];
                mma16(acc[0][na], a0, b);
                mma16(acc[1][na], a1, b);
            }
        }
        buf ^= 1;
        __syncthreads();
    }
}

// ---------------- QKV projection + RoPE ----------------
__global__ void __launch_bounds__(256) qkv_kernel() {
    extern __shared__ unsigned gsm[];
    unsigned* As = gsm;
    unsigned* Ws = gsm + 2 * 128 * WSTR;

    const int z = blockIdx.z;
    const __half* Wt = (z == 0) ? g_Wqh : ((z == 1) ? g_Wkh : g_Wvh);

    const int tid = threadIdx.x;
    const int lane = tid & 31;
    const int warp = tid >> 5;
    const int wm = warp & 3;
    const int wn = warp >> 2;
    const int gid = lane >> 2;
    const int tig = lane & 3;
    const int s0 = blockIdx.y * 128;
    const int n0 = blockIdx.x * 64;
    const int head = blockIdx.x;
    const float qscale = (z == 0) ? 0.125f : 1.0f;

    float acc[2][4][4] = {};
    gemm_core_128x64(g_xh, Wt, s0, n0, acc, As, Ws);

#pragma unroll
    for (int ma = 0; ma < 2; ma++) {
#pragma unroll
        for (int na = 0; na < 4; na++) {
#pragma unroll
            for (int rr = 0; rr < 2; rr++) {
                int row = s0 + wm * 32 + ma * 16 + gid + rr * 8;
                int d = wn * 32 + na * 8 + 2 * tig;
                float v0 = acc[ma][na][2 * rr + 0];
                float v1 = acc[ma][na][2 * rr + 1];
                if (z < 2) {
                    float2 c = *(const float2*)&g_cos[row * HD + d];
                    float2 s = *(const float2*)&g_sin[row * HD + d];
                    float o0 = (v0 * c.x - v1 * s.x) * qscale;
                    float o1 = (v1 * c.y + v0 * s.y) * qscale;
                    __half* dst = (z == 0) ? g_Qh : g_Kh;
                    *(unsigned*)&dst[(size_t)head * SEQ * HD + (size_t)row * HD + d] =
                        packh2(o0, o1);
                } else {
                    // V: store transposed [h][d][s]
                    size_t base = (size_t)head * SEQ * HD;
                    g_Vh[base + (size_t)d * SEQ + row] = __float2half_rn(v0);
                    g_Vh[base + (size_t)(d + 1) * SEQ + row] = __float2half_rn(v1);
                }
            }
        }
    }
}

// ---------------- output projection ----------------
__global__ void __launch_bounds__(256) oproj_kernel(float* __restrict__ out) {
    extern __shared__ unsigned gsm[];
    unsigned* As = gsm;
    unsigned* Ws = gsm + 2 * 128 * WSTR;

    const int tid = threadIdx.x;
    const int lane = tid & 31;
    const int warp = tid >> 5;
    const int wm = warp & 3;
    const int wn = warp >> 2;
    const int gid = lane >> 2;
    const int tig = lane & 3;
    const int s0 = blockIdx.y * 128;
    const int n0 = blockIdx.x * 64;

    float acc[2][4][4] = {};
    gemm_core_128x64(g_ctxh, g_Woh, s0, n0, acc, As, Ws);

#pragma unroll
    for (int ma = 0; ma < 2; ma++)
#pragma unroll
        for (int na = 0; na < 4; na++)
#pragma unroll
            for (int rr = 0; rr < 2; rr++) {
                int row = s0 + wm * 32 + ma * 16 + gid + rr * 8;
                int col = n0 + wn * 32 + na * 8 + 2 * tig;
                *(float2*)&out[(size_t)row * HDIM + col] =
                    make_float2(acc[ma][na][2 * rr + 0], acc[ma][na][2 * rr + 1]);
            }
}

// ---------------- flash attention: fp16 m16n8k16, 8 warps x m16 ----------------
#define ATT_SMEM ((128 * WSTR + 2 * 64 * WSTR + 2 * 64 * WSTR) * 4 + 2 * 64 * 4)

__global__ void __launch_bounds__(256, 2) attn_kernel(const int* __restrict__ mask) {
    extern __shared__ unsigned sm_u[];
    unsigned* Qs = sm_u;                              // 128 x WSTR
    unsigned* Ks = Qs + 128 * WSTR;                   // 2 x 64 x WSTR
    unsigned* Vs = Ks + 2 * 64 * WSTR;                // 2 x 64 x WSTR (transposed: rows d)
    int* smask = (int*)(Vs + 2 * 64 * WSTR);          // 2 x 64

    const int tid = threadIdx.x;
    const int lane = tid & 31;
    const int w = tid >> 5;
    const int gid = lane >> 2;
    const int tig = lane & 3;
    const int q0 = blockIdx.x * 128;
    const int h = blockIdx.y;
    const int qb = w * 16;

    const __half* Qg = g_Qh + (size_t)h * SEQ * HD;
    const __half* Kg = g_Kh + (size_t)h * SEQ * HD;
    const __half* Vg = g_Vh + (size_t)h * SEQ * HD;   // [d][s]

    unsigned ksb = (unsigned)__cvta_generic_to_shared(Ks);
    unsigned vsb = (unsigned)__cvta_generic_to_shared(Vs);
    unsigned msb = (unsigned)__cvta_generic_to_shared(smask);

    auto issue_kv = [&](int kt, int buf) {
        int k0 = kt * 64;
#pragma unroll
        for (int i = 0; i < 2; i++) {                 // 64 rows x 8 chunks each
            int f = tid + 256 * i;
            int row = f >> 3, ch = f & 7;
            cp16(ksb + (unsigned)(buf * 64 * WSTR + row * WSTR + ch * 4) * 4u,
                 &Kg[(size_t)(k0 + row) * HD + ch * 8]);
            cp16(vsb + (unsigned)(buf * 64 * WSTR + row * WSTR + ch * 4) * 4u,
                 &Vg[(size_t)row * SEQ + k0 + ch * 8]);
        }
        if (tid < 64) cp4(msb + (unsigned)(buf * 64 + tid) * 4u, &mask[k0 + tid]);
    };

    // stage Q once (fp16, pre-scaled)
#pragma unroll
    for (int i = 0; i < 4; i++) {
        int f = tid + 256 * i;
        int row = f >> 3, ch = f & 7;
        *(uint4*)&Qs[row * WSTR + ch * 4] =
            *(const uint4*)&Qg[(size_t)(q0 + row) * HD + ch * 8];
    }

    float Oacc[8][4] = {};
    float mrow[2] = {-1e30f, -1e30f};
    float lrow[2] = {0.f, 0.f};

    issue_kv(0, 0);
    asm volatile("cp.async.commit_group;");
    int buf = 0;

    for (int kt = 0; kt < SEQ / 64; kt++) {
        if (kt + 1 < SEQ / 64) {
            issue_kv(kt + 1, buf ^ 1);
            asm volatile("cp.async.commit_group;");
            asm volatile("cp.async.wait_group 1;");
        } else {
            asm volatile("cp.async.wait_group 0;");
        }
        __syncthreads();

        const unsigned* Kf = Ks + buf * 64 * WSTR;
        const unsigned* Vf = Vs + buf * 64 * WSTR;
        const int* Mf = smask + buf * 64;

        // ---- S = Q K^T ----
        float sacc[8][4] = {};
#pragma unroll
        for (int kg = 0; kg < 4; kg++) {
            unsigned a[4];
            a[0] = Qs[(qb + gid) * WSTR + kg * 8 + tig];
            a[1] = Qs[(qb + gid + 8) * WSTR + kg * 8 + tig];
            a[2] = Qs[(qb + gid) * WSTR + kg * 8 + tig + 4];
            a[3] = Qs[(qb + gid + 8) * WSTR + kg * 8 + tig + 4];
#pragma unroll
            for (int na = 0; na < 8; na++) {
                unsigned b[2];
                int key = na * 8 + gid;
                b[0] = Kf[key * WSTR + kg * 8 + tig];
                b[1] = Kf[key * WSTR + kg * 8 + tig + 4];
                mma16(sacc[na], a, b);
            }
        }

        // ---- mask bias (skip when tile all-ones) ----
        bool localz = false;
        float bb[8][2];
#pragma unroll
        for (int na = 0; na < 8; na++) {
            int m0 = Mf[na * 8 + 2 * tig];
            int m1 = Mf[na * 8 + 2 * tig + 1];
            bb[na][0] = (m0 == 0) ? -1e30f : 0.f;
            bb[na][1] = (m1 == 0) ? -1e30f : 0.f;
            localz |= (m0 == 0) | (m1 == 0);
        }
        if (__any_sync(0xffffffffu, localz)) {
#pragma unroll
            for (int na = 0; na < 8; na++)
#pragma unroll
                for (int rr = 0; rr < 2; rr++) {
                    sacc[na][2 * rr + 0] += bb[na][0];
                    sacc[na][2 * rr + 1] += bb[na][1];
                }
        }

        // ---- online softmax (rows gid, gid+8) ----
#pragma unroll
        for (int rr = 0; rr < 2; rr++) {
            float mt = -1e30f;
#pragma unroll
            for (int na = 0; na < 8; na++)
                mt = fmaxf(mt, fmaxf(sacc[na][2 * rr], sacc[na][2 * rr + 1]));
            mt = fmaxf(mt, __shfl_xor_sync(0xffffffffu, mt, 1));
            mt = fmaxf(mt, __shfl_xor_sync(0xffffffffu, mt, 2));
            float mnew = fmaxf(mrow[rr], mt);
            float corr = __expf(mrow[rr] - mnew);
            float rs = 0.f;
#pragma unroll
            for (int na = 0; na < 8; na++) {
#pragma unroll
                for (int s = 0; s < 2; s++) {
                    float p = __expf(sacc[na][2 * rr + s] - mnew);
                    sacc[na][2 * rr + s] = p;
                    rs += p;
                }
            }
            rs += __shfl_xor_sync(0xffffffffu, rs, 1);
            rs += __shfl_xor_sync(0xffffffffu, rs, 2);
            lrow[rr] = lrow[rr] * corr + rs;
            mrow[rr] = mnew;
#pragma unroll
            for (int nd = 0; nd < 8; nd++) {
                Oacc[nd][2 * rr + 0] *= corr;
                Oacc[nd][2 * rr + 1] *= corr;
            }
        }

        // ---- O += P V : C-frag maps DIRECTLY to fp16 A-frag (no shuffles) ----
#pragma unroll
        for (int kg = 0; kg < 4; kg++) {
            unsigned aP[4];
            aP[0] = packh2(sacc[2 * kg][0], sacc[2 * kg][1]);
            aP[1] = packh2(sacc[2 * kg][2], sacc[2 * kg][3]);
            aP[2] = packh2(sacc[2 * kg + 1][0], sacc[2 * kg + 1][1]);
            aP[3] = packh2(sacc[2 * kg + 1][2], sacc[2 * kg + 1][3]);
#pragma unroll
            for (int nd = 0; nd < 8; nd++) {
                unsigned b[2];
                int d = nd * 8 + gid;
                b[0] = Vf[d * WSTR + kg * 8 + tig];
                b[1] = Vf[d * WSTR + kg * 8 + tig + 4];
                mma16(Oacc[nd], aP, b);
            }
        }
        buf ^= 1;
        __syncthreads();
    }

    // epilogue: normalize, write ctx fp16
    float inv[2] = {1.0f / lrow[0], 1.0f / lrow[1]};
#pragma unroll
    for (int nd = 0; nd < 8; nd++)
#pragma unroll
        for (int rr = 0; rr < 2; rr++) {
            int row = q0 + qb + gid + rr * 8;
            int d = nd * 8 + 2 * tig;
            float iv = inv[rr];
            *(unsigned*)&g_ctxh[(size_t)row * HDIM + h * HD + d] =
                packh2(Oacc[nd][2 * rr] * iv, Oacc[nd][2 * rr + 1] * iv);
        }
}

// ---------------- launch ----------------
extern "C" void kernel_launch(void* const* d_in, const int* in_sizes, int n_in,
                              void* d_out, int out_size) {
    const float* x  = (const float*)d_in[0];
    const float* Wq = (const float*)d_in[1];
    const float* Wk = (const float*)d_in[2];
    const float* Wv = (const float*)d_in[3];
    const float* Wo = (const float*)d_in[4];
    const int* mask = (const int*)d_in[5];
    float* out = (float*)d_out;

    cudaFuncSetAttribute(qkv_kernel,
                         cudaFuncAttributeMaxDynamicSharedMemorySize, GEMM_SMEM);
    cudaFuncSetAttribute(oproj_kernel,
                         cudaFuncAttributeMaxDynamicSharedMemorySize, GEMM_SMEM);
    cudaFuncSetAttribute(attn_kernel,
                         cudaFuncAttributeMaxDynamicSharedMemorySize, ATT_SMEM);

    x2h_kernel<<<SEQ * HDIM / 4 / 256, 256>>>(x);
    wtrans_kernel<<<dim3(HDIM / 64, HDIM / 64, 4), 256>>>(Wq, Wk, Wv, Wo);
    rope_tables_kernel<<<(SEQ * HD + 255) / 256, 256>>>();
    qkv_kernel<<<dim3(NH, SEQ / 128, 3), 256, GEMM_SMEM>>>();
    attn_kernel<<<dim3(SEQ / 128, NH), 256, ATT_SMEM>>>(mask);
    oproj_kernel<<<dim3(HDIM / 64, SEQ / 128), 256, GEMM_SMEM>>>(out);
}

// round 9
// speedup vs baseline: 6.1986x; 1.0827x over previous
#include <cuda_runtime.h>
#include <cuda_fp16.h>
#include <math.h>

#define SEQ 4096
#define HDIM 1024
#define NH 16
#define HD 64
#define WSTR 36   // smem word stride (36 words = 72 halves) for 64-half-wide rows

// ---------------- device scratch (fp16 operands, fp32 tables) ----------------
__device__ __half g_Qh[NH * SEQ * HD];    // [h][s][d], pre-scaled by 0.125*log2(e)
__device__ __half g_Kh[NH * SEQ * HD];    // [h][s][d]
__device__ __half g_Vh[NH * SEQ * HD];    // [h][d][s]  TRANSPOSED
__device__ __half g_ctxh[SEQ * HDIM];     // [s][h*64+d]
__device__ __half g_xh[SEQ * HDIM];
__device__ __half g_Wqh[HDIM * HDIM];     // transposed [n][k]
__device__ __half g_Wkh[HDIM * HDIM];
__device__ __half g_Wvh[HDIM * HDIM];
__device__ __half g_Woh[HDIM * HDIM];
__device__ float g_cos[SEQ * HD];
__device__ float g_sin[SEQ * HD];

// ---------------- helpers ----------------
__device__ __forceinline__ void mma16(float* c, const unsigned* a, const unsigned* b) {
    asm volatile(
        "mma.sync.aligned.m16n8k16.row.col.f32.f16.f16.f32 "
        "{%0,%1,%2,%3}, {%4,%5,%6,%7}, {%8,%9}, {%0,%1,%2,%3};\n"
        : "+f"(c[0]), "+f"(c[1]), "+f"(c[2]), "+f"(c[3])
        : "r"(a[0]), "r"(a[1]), "r"(a[2]), "r"(a[3]), "r"(b[0]), "r"(b[1]));
}

__device__ __forceinline__ void ldm_x4(unsigned* r, unsigned addr) {
    asm volatile("ldmatrix.sync.aligned.m8n8.x4.shared.b16 {%0,%1,%2,%3}, [%4];"
                 : "=r"(r[0]), "=r"(r[1]), "=r"(r[2]), "=r"(r[3]) : "r"(addr));
}

__device__ __forceinline__ unsigned packh2(float lo, float hi) {
    __half2 h = __floats2half2_rn(lo, hi);
    return *(unsigned*)&h;
}

__device__ __forceinline__ void cp16(unsigned dst, const void* src) {
    asm volatile("cp.async.cg.shared.global [%0], [%1], 16;" :: "r"(dst), "l"(src));
}
__device__ __forceinline__ void cp4(unsigned dst, const void* src) {
    asm volatile("cp.async.ca.shared.global [%0], [%1], 4;" :: "r"(dst), "l"(src));
}

// ---------------- prep kernels ----------------
__global__ void x2h_kernel(const float* __restrict__ x) {
    int i = blockIdx.x * 256 + threadIdx.x;
    float4 v = ((const float4*)x)[i];
    uint2 u;
    u.x = packh2(v.x, v.y);
    u.y = packh2(v.z, v.w);
    ((uint2*)g_xh)[i] = u;
}

__global__ void wtrans_kernel(const float* __restrict__ Wq,
                              const float* __restrict__ Wk,
                              const float* __restrict__ Wv,
                              const float* __restrict__ Wo) {
    __shared__ float tile[64][65];
    const int z = blockIdx.z;
    const float* W = (z == 0) ? Wq : (z == 1) ? Wk : (z == 2) ? Wv : Wo;
    __half* Wt = (z == 0) ? g_Wqh : (z == 1) ? g_Wkh : (z == 2) ? g_Wvh : g_Woh;
    const int k0 = blockIdx.x * 64, n0 = blockIdx.y * 64;
    const int tid = threadIdx.x;
#pragma unroll
    for (int i = 0; i < 16; i++) {
        int idx = tid + 256 * i;
        int r = idx >> 6, c = idx & 63;
        tile[r][c] = W[(size_t)(k0 + r) * HDIM + n0 + c];
    }
    __syncthreads();
#pragma unroll
    for (int i = 0; i < 16; i++) {
        int idx = tid + 256 * i;
        int r = idx >> 6, c = idx & 63;
        Wt[(size_t)(n0 + r) * HDIM + k0 + c] = __float2half_rn(tile[c][r]);
    }
}

// ---------------- RoPE tables ----------------
__global__ void rope_tables_kernel() {
    int idx = blockIdx.x * 256 + threadIdx.x;
    if (idx >= SEQ * HD) return;
    int t = idx >> 6;
    int j = idx & 63;
    int i = j & 31;
    float xe = (float)(2 * i) / 64.0f;
    float pf = (float)pow(10000.0, (double)xe);
    float invf = 1.0f / pf;
    float angf = (float)t * invf;
    double ang = (double)angf;
    g_cos[idx] = (float)cos(ang);
    g_sin[idx] = (float)sin(ang);
}

// ---------------- fp16 GEMM core (ldmatrix fragments) ----------------
#define GEMM_SMEM ((2 * 128 * WSTR + 2 * 64 * WSTR) * 4)

__device__ __forceinline__ void gemm_core_128x64(
    const __half* __restrict__ A, const __half* __restrict__ Wt,
    int s0, int n0, float acc[2][4][4], unsigned* As, unsigned* Ws)
{
    const int tid = threadIdx.x;
    const int lane = tid & 31;
    const int warp = tid >> 5;
    const int wm = warp & 3;
    const int wn = warp >> 2;
    const int qb = wm * 32;

    unsigned asb = (unsigned)__cvta_generic_to_shared(As);
    unsigned bsb = (unsigned)__cvta_generic_to_shared(Ws);

    // ldmatrix lane address patterns
    const int arow = lane & 15;                 // A: row within 16-block
    const int acolw = (lane >> 4) * 4;          // A: word offset (k half)
    const int brow = ((lane & 16) ? 8 : 0) + (lane & 7);   // B: row within 16-block
    const int bcolw = ((lane >> 3) & 1) * 4;    // B: word offset

    auto issue = [&](int k0, int buf) {
#pragma unroll
        for (int i = 0; i < 4; i++) {
            int f = tid + 256 * i;
            int row = f >> 3, ch = f & 7;
            cp16(asb + (unsigned)(buf * 128 * WSTR + row * WSTR + ch * 4) * 4u,
                 &A[(size_t)(s0 + row) * HDIM + k0 + ch * 8]);
        }
#pragma unroll
        for (int i = 0; i < 2; i++) {
            int f = tid + 256 * i;
            int row = f >> 3, ch = f & 7;
            cp16(bsb + (unsigned)(buf * 64 * WSTR + row * WSTR + ch * 4) * 4u,
                 &Wt[(size_t)(n0 + row) * HDIM + k0 + ch * 8]);
        }
    };

    issue(0, 0);
    asm volatile("cp.async.commit_group;");
    int buf = 0;

    for (int k0 = 0; k0 < HDIM; k0 += 64) {
        if (k0 + 64 < HDIM) {
            issue(k0 + 64, buf ^ 1);
            asm volatile("cp.async.commit_group;");
            asm volatile("cp.async.wait_group 1;");
        } else {
            asm volatile("cp.async.wait_group 0;");
        }
        __syncthreads();

        unsigned a_base0 = asb + (unsigned)(buf * 128 * WSTR + (qb + arow) * WSTR + acolw) * 4u;
        unsigned a_base1 = a_base0 + (unsigned)(16 * WSTR) * 4u;
        unsigned b_base = bsb + (unsigned)(buf * 64 * WSTR + (wn * 32 + brow) * WSTR + bcolw) * 4u;

#pragma unroll
        for (int kg = 0; kg < 4; kg++) {
            unsigned a0[4], a1[4];
            ldm_x4(a0, a_base0 + kg * 32u);
            ldm_x4(a1, a_base1 + kg * 32u);
#pragma unroll
            for (int nb = 0; nb < 2; nb++) {
                unsigned b[4];
                ldm_x4(b, b_base + (unsigned)(nb * 16 * WSTR) * 4u + kg * 32u);
                mma16(acc[0][2 * nb], a0, b);
                mma16(acc[0][2 * nb + 1], a0, b + 2);
                mma16(acc[1][2 * nb], a1, b);
                mma16(acc[1][2 * nb + 1], a1, b + 2);
            }
        }
        buf ^= 1;
        __syncthreads();
    }
}

// ---------------- QKV projection + RoPE ----------------
#define LOG2E 1.44269504088896340736f

__global__ void __launch_bounds__(256) qkv_kernel() {
    extern __shared__ unsigned gsm[];
    unsigned* As = gsm;
    unsigned* Ws = gsm + 2 * 128 * WSTR;

    const int z = blockIdx.z;
    const __half* Wt = (z == 0) ? g_Wqh : ((z == 1) ? g_Wkh : g_Wvh);

    const int tid = threadIdx.x;
    const int lane = tid & 31;
    const int warp = tid >> 5;
    const int wm = warp & 3;
    const int wn = warp >> 2;
    const int gid = lane >> 2;
    const int tig = lane & 3;
    const int s0 = blockIdx.y * 128;
    const int n0 = blockIdx.x * 64;
    const int head = blockIdx.x;
    const float qscale = (z == 0) ? 0.125f * LOG2E : 1.0f;   // fold 1/sqrt(hd) * log2(e)

    float acc[2][4][4] = {};
    gemm_core_128x64(g_xh, Wt, s0, n0, acc, As, Ws);

    // C-frag mapping: na even -> n = nb*16 + gid, na odd -> n = nb*16 + 8 + gid
#pragma unroll
    for (int ma = 0; ma < 2; ma++) {
#pragma unroll
        for (int na = 0; na < 4; na++) {
#pragma unroll
            for (int rr = 0; rr < 2; rr++) {
                int row = s0 + wm * 32 + ma * 16 + gid + rr * 8;
                int d = wn * 32 + na * 8 + 2 * tig;
                float v0 = acc[ma][na][2 * rr + 0];
                float v1 = acc[ma][na][2 * rr + 1];
                if (z < 2) {
                    float2 c = *(const float2*)&g_cos[row * HD + d];
                    float2 s = *(const float2*)&g_sin[row * HD + d];
                    float o0 = (v0 * c.x - v1 * s.x) * qscale;
                    float o1 = (v1 * c.y + v0 * s.y) * qscale;
                    __half* dst = (z == 0) ? g_Qh : g_Kh;
                    *(unsigned*)&dst[(size_t)head * SEQ * HD + (size_t)row * HD + d] =
                        packh2(o0, o1);
                } else {
                    size_t base = (size_t)head * SEQ * HD;
                    g_Vh[base + (size_t)d * SEQ + row] = __float2half_rn(v0);
                    g_Vh[base + (size_t)(d + 1) * SEQ + row] = __float2half_rn(v1);
                }
            }
        }
    }
}

// ---------------- output projection ----------------
__global__ void __launch_bounds__(256) oproj_kernel(float* __restrict__ out) {
    extern __shared__ unsigned gsm[];
    unsigned* As = gsm;
    unsigned* Ws = gsm + 2 * 128 * WSTR;

    const int tid = threadIdx.x;
    const int lane = tid & 31;
    const int warp = tid >> 5;
    const int wm = warp & 3;
    const int wn = warp >> 2;
    const int gid = lane >> 2;
    const int tig = lane & 3;
    const int s0 = blockIdx.y * 128;
    const int n0 = blockIdx.x * 64;

    float acc[2][4][4] = {};
    gemm_core_128x64(g_ctxh, g_Woh, s0, n0, acc, As, Ws);

#pragma unroll
    for (int ma = 0; ma < 2; ma++)
#pragma unroll
        for (int na = 0; na < 4; na++)
#pragma unroll
            for (int rr = 0; rr < 2; rr++) {
                int row = s0 + wm * 32 + ma * 16 + gid + rr * 8;
                int col = n0 + wn * 32 + na * 8 + 2 * tig;
                *(float2*)&out[(size_t)row * HDIM + col] =
                    make_float2(acc[ma][na][2 * rr + 0], acc[ma][na][2 * rr + 1]);
            }
}

// ---------------- flash attention: fp16 + ldmatrix, softmax in exp2 domain ----------------
#define ATT_SMEM ((128 * WSTR + 2 * 64 * WSTR + 2 * 64 * WSTR) * 4 + 2 * 64 * 4)

__global__ void __launch_bounds__(256, 2) attn_kernel(const int* __restrict__ mask) {
    extern __shared__ unsigned sm_u[];
    unsigned* Qs = sm_u;                              // 128 x WSTR
    unsigned* Ks = Qs + 128 * WSTR;                   // 2 x 64 x WSTR
    unsigned* Vs = Ks + 2 * 64 * WSTR;                // 2 x 64 x WSTR (rows = d)
    int* smask = (int*)(Vs + 2 * 64 * WSTR);          // 2 x 64

    const int tid = threadIdx.x;
    const int lane = tid & 31;
    const int w = tid >> 5;
    const int gid = lane >> 2;
    const int tig = lane & 3;
    const int q0 = blockIdx.x * 128;
    const int h = blockIdx.y;
    const int qb = w * 16;

    const __half* Qg = g_Qh + (size_t)h * SEQ * HD;
    const __half* Kg = g_Kh + (size_t)h * SEQ * HD;
    const __half* Vg = g_Vh + (size_t)h * SEQ * HD;   // [d][s]

    unsigned qsb = (unsigned)__cvta_generic_to_shared(Qs);
    unsigned ksb = (unsigned)__cvta_generic_to_shared(Ks);
    unsigned vsb = (unsigned)__cvta_generic_to_shared(Vs);
    unsigned msb = (unsigned)__cvta_generic_to_shared(smask);

    const int arow = lane & 15;
    const int acolw = (lane >> 4) * 4;
    const int brow = ((lane & 16) ? 8 : 0) + (lane & 7);
    const int bcolw = ((lane >> 3) & 1) * 4;

    auto issue_kv = [&](int kt, int buf) {
        int k0 = kt * 64;
#pragma unroll
        for (int i = 0; i < 2; i++) {
            int f = tid + 256 * i;
            int row = f >> 3, ch = f & 7;
            cp16(ksb + (unsigned)(buf * 64 * WSTR + row * WSTR + ch * 4) * 4u,
                 &Kg[(size_t)(k0 + row) * HD + ch * 8]);
            cp16(vsb + (unsigned)(buf * 64 * WSTR + row * WSTR + ch * 4) * 4u,
                 &Vg[(size_t)row * SEQ + k0 + ch * 8]);
        }
        if (tid < 64) cp4(msb + (unsigned)(buf * 64 + tid) * 4u, &mask[k0 + tid]);
    };

    // stage Q once
#pragma unroll
    for (int i = 0; i < 4; i++) {
        int f = tid + 256 * i;
        int row = f >> 3, ch = f & 7;
        *(uint4*)&Qs[row * WSTR + ch * 4] =
            *(const uint4*)&Qg[(size_t)(q0 + row) * HD + ch * 8];
    }

    float Oacc[8][4] = {};
    float mrow[2] = {-1e30f, -1e30f};
    float lrow[2] = {0.f, 0.f};

    issue_kv(0, 0);
    asm volatile("cp.async.commit_group;");
    int buf = 0;

    const unsigned qaddr = qsb + (unsigned)((qb + arow) * WSTR + acolw) * 4u;

    for (int kt = 0; kt < SEQ / 64; kt++) {
        if (kt + 1 < SEQ / 64) {
            issue_kv(kt + 1, buf ^ 1);
            asm volatile("cp.async.commit_group;");
            asm volatile("cp.async.wait_group 1;");
        } else {
            asm volatile("cp.async.wait_group 0;");
        }
        __syncthreads();

        const unsigned kbase = ksb + (unsigned)(buf * 64 * WSTR + brow * WSTR + bcolw) * 4u;
        const unsigned vbase = vsb + (unsigned)(buf * 64 * WSTR + brow * WSTR + bcolw) * 4u;
        const int* Mf = smask + buf * 64;

        // ---- S = Q K^T ----
        float sacc[8][4] = {};
#pragma unroll
        for (int kg = 0; kg < 4; kg++) {
            unsigned a[4];
            ldm_x4(a, qaddr + kg * 32u);
#pragma unroll
            for (int nb = 0; nb < 4; nb++) {
                unsigned b[4];
                ldm_x4(b, kbase + (unsigned)(nb * 16 * WSTR) * 4u + kg * 32u);
                mma16(sacc[2 * nb], a, b);
                mma16(sacc[2 * nb + 1], a, b + 2);
            }
        }

        // ---- mask bias (skip when tile all-ones) ----
        bool localz = false;
        float bb[8][2];
#pragma unroll
        for (int na = 0; na < 8; na++) {
            int m0 = Mf[na * 8 + 2 * tig];
            int m1 = Mf[na * 8 + 2 * tig + 1];
            bb[na][0] = (m0 == 0) ? -1e30f : 0.f;
            bb[na][1] = (m1 == 0) ? -1e30f : 0.f;
            localz |= (m0 == 0) | (m1 == 0);
        }
        if (__any_sync(0xffffffffu, localz)) {
#pragma unroll
            for (int na = 0; na < 8; na++)
#pragma unroll
                for (int rr = 0; rr < 2; rr++) {
                    sacc[na][2 * rr + 0] += bb[na][0];
                    sacc[na][2 * rr + 1] += bb[na][1];
                }
        }

        // ---- online softmax in exp2 domain (S already scaled by log2e) ----
#pragma unroll
        for (int rr = 0; rr < 2; rr++) {
            float mt = -1e30f;
#pragma unroll
            for (int na = 0; na < 8; na++)
                mt = fmaxf(mt, fmaxf(sacc[na][2 * rr], sacc[na][2 * rr + 1]));
            mt = fmaxf(mt, __shfl_xor_sync(0xffffffffu, mt, 1));
            mt = fmaxf(mt, __shfl_xor_sync(0xffffffffu, mt, 2));
            float mnew = fmaxf(mrow[rr], mt);
            float corr = exp2f(mrow[rr] - mnew);
            float rs = 0.f;
#pragma unroll
            for (int na = 0; na < 8; na++) {
#pragma unroll
                for (int s = 0; s < 2; s++) {
                    float p = exp2f(sacc[na][2 * rr + s] - mnew);
                    sacc[na][2 * rr + s] = p;
                    rs += p;
                }
            }
            rs += __shfl_xor_sync(0xffffffffu, rs, 1);
            rs += __shfl_xor_sync(0xffffffffu, rs, 2);
            lrow[rr] = lrow[rr] * corr + rs;
            mrow[rr] = mnew;
#pragma unroll
            for (int nd = 0; nd < 8; nd++) {
                Oacc[nd][2 * rr + 0] *= corr;
                Oacc[nd][2 * rr + 1] *= corr;
            }
        }

        // ---- O += P V (C-frag -> A-frag direct pack; V b-frags via ldmatrix) ----
#pragma unroll
        for (int kg = 0; kg < 4; kg++) {
            unsigned aP[4];
            aP[0] = packh2(sacc[2 * kg][0], sacc[2 * kg][1]);
            aP[1] = packh2(sacc[2 * kg][2], sacc[2 * kg][3]);
            aP[2] = packh2(sacc[2 * kg + 1][0], sacc[2 * kg + 1][1]);
            aP[3] = packh2(sacc[2 * kg + 1][2], sacc[2 * kg + 1][3]);
#pragma unroll
            for (int nb = 0; nb < 4; nb++) {
                unsigned b[4];
                ldm_x4(b, vbase + (unsigned)(nb * 16 * WSTR) * 4u + kg * 32u);
                mma16(Oacc[2 * nb], aP, b);
                mma16(Oacc[2 * nb + 1], aP, b + 2);
            }
        }
        buf ^= 1;
        __syncthreads();
    }

    // epilogue: normalize, write ctx fp16
    float inv[2] = {1.0f / lrow[0], 1.0f / lrow[1]};
#pragma unroll
    for (int nd = 0; nd < 8; nd++)
#pragma unroll
        for (int rr = 0; rr < 2; rr++) {
            int row = q0 + qb + gid + rr * 8;
            int d = nd * 8 + 2 * tig;
            float iv = inv[rr];
            *(unsigned*)&g_ctxh[(size_t)row * HDIM + h * HD + d] =
                packh2(Oacc[nd][2 * rr] * iv, Oacc[nd][2 * rr + 1] * iv);
        }
}

// ---------------- launch ----------------
extern "C" void kernel_launch(void* const* d_in, const int* in_sizes, int n_in,
                              void* d_out, int out_size) {
    const float* x  = (const float*)d_in[0];
    const float* Wq = (const float*)d_in[1];
    const float* Wk = (const float*)d_in[2];
    const float* Wv = (const float*)d_in[3];
    const float* Wo = (const float*)d_in[4];
    const int* mask = (const int*)d_in[5];
    float* out = (float*)d_out;

    cudaFuncSetAttribute(qkv_kernel,
                         cudaFuncAttributeMaxDynamicSharedMemorySize, GEMM_SMEM);
    cudaFuncSetAttribute(oproj_kernel,
                         cudaFuncAttributeMaxDynamicSharedMemorySize, GEMM_SMEM);
    cudaFuncSetAttribute(attn_kernel,
                         cudaFuncAttributeMaxDynamicSharedMemorySize, ATT_SMEM);

    x2h_kernel<<<SEQ * HDIM / 4 / 256, 256>>>(x);
    wtrans_kernel<<<dim3(HDIM / 64, HDIM / 64, 4), 256>>>(Wq, Wk, Wv, Wo);
    rope_tables_kernel<<<(SEQ * HD + 255) / 256, 256>>>();
    qkv_kernel<<<dim3(NH, SEQ / 128, 3), 256, GEMM_SMEM>>>();
    attn_kernel<<<dim3(SEQ / 128, NH), 256, ATT_SMEM>>>(mask);
    oproj_kernel<<<dim3(HDIM / 64, SEQ / 128), 256, GEMM_SMEM>>>(out);
}